// round 6
// baseline (speedup 1.0000x reference)
#include <cuda_runtime.h>
#include <cstdint>

#define SS 512
#define BB 64
#define HH 1024
#define EE 512
#define VV 32000
#define TWOH 2048
#define KTOT 3584
#define G4 4096
#define NCHUNK 64
#define CROWS 8
#define NSPLIT 7
#define KSPLIT 512

// HMMA GEMM tile config
#define MT 128              // m rows per CTA (weight rows)
#define KC 64               // k per chunk
#define ROWB 144            // smem row stride bytes (9 granules -> conflict-free)
#define OFF_AHI 0
#define OFF_ALO 18432       // 128*144
#define OFF_BHI 36864
#define OFF_BLO 46080       // + 64*144
#define STAGE 55296

// ---------------- scratch ----------------------------------------------------
__device__ float g_hw[BB];
__device__ float g_eM[BB * NCHUNK];
__device__ float g_eL[BB * NCHUNK];
__device__ float g_ctx[(size_t)BB * NCHUNK * TWOH];
__device__ unsigned short g_Bhi[BB * KTOT];   // rnn_in bf16 hi  [b][k]
__device__ unsigned short g_Blo[BB * KTOT];
__device__ unsigned short g_h1hi[BB * HH];
__device__ unsigned short g_h1lo[BB * HH];
__device__ float g_gatesP[NSPLIT * G4 * BB];  // [s][m][b]

__device__ __forceinline__ float sigm(float x) { return 1.f / (1.f + __expf(-x)); }

__device__ __forceinline__ void cpa16(uint32_t s, const void* g) {
    asm volatile("cp.async.cg.shared.global [%0], [%1], 16;" :: "r"(s), "l"(g));
}
__device__ __forceinline__ void cpa_commit() { asm volatile("cp.async.commit_group;"); }
__device__ __forceinline__ void cpa_wait0()  { asm volatile("cp.async.wait_group 0;"); }

__device__ __forceinline__ void ldsm4(uint32_t* r, uint32_t addr) {
    asm volatile("ldmatrix.sync.aligned.m8n8.x4.shared.b16 {%0,%1,%2,%3}, [%4];"
        : "=r"(r[0]), "=r"(r[1]), "=r"(r[2]), "=r"(r[3]) : "r"(addr));
}
__device__ __forceinline__ void mma16816(float* d, const uint32_t* a, const uint32_t* b) {
    asm volatile("mma.sync.aligned.m16n8k16.row.col.f32.bf16.bf16.f32 "
        "{%0,%1,%2,%3},{%4,%5,%6,%7},{%8,%9},{%0,%1,%2,%3};"
        : "+f"(d[0]), "+f"(d[1]), "+f"(d[2]), "+f"(d[3])
        : "r"(a[0]), "r"(a[1]), "r"(a[2]), "r"(a[3]), "r"(b[0]), "r"(b[1]));
}
__device__ __forceinline__ void st4(uint32_t a, uint32_t x, uint32_t y, uint32_t z, uint32_t w) {
    asm volatile("st.shared.v4.u32 [%0], {%1,%2,%3,%4};" :: "r"(a), "r"(x), "r"(y), "r"(z), "r"(w));
}

__device__ __forceinline__ void split16(float x, unsigned short& hi, unsigned short& lo) {
    uint32_t bx = __float_as_uint(x);
    hi = (unsigned short)(bx >> 16);
    float lf = x - __uint_as_float(bx & 0xFFFF0000u);
    lo = (unsigned short)(__float_as_uint(lf) >> 16);
}

// ---------------- K0 ----------------------------------------------------------
__global__ void k_hw(const float* __restrict__ hidden, const float* __restrict__ Wen) {
    int b = blockIdx.x, tid = threadIdx.x;
    float p = 0.f;
    for (int k = tid; k < HH; k += 128) p += hidden[b * HH + k] * Wen[k];
    __shared__ float red[128];
    red[tid] = p; __syncthreads();
    for (int o = 64; o >= 32; o >>= 1) { if (tid < o) red[tid] += red[tid + o]; __syncthreads(); }
    if (tid < 32) {
        float v = red[tid];
        for (int o = 16; o; o >>= 1) v += __shfl_xor_sync(~0u, v, o);
        if (tid == 0) g_hw[b] = v;
    }
}

// ---------------- K1: attention --------------------------------------------
__global__ __launch_bounds__(256)
void k_attn(const float* __restrict__ enc, const float* __restrict__ Wen,
            const float* __restrict__ be) {
    extern __shared__ float sm[];
    float* rows = sm;
    float* we   = sm + CROWS * TWOH;
    __shared__ float sE[CROWS];
    const int chunk = blockIdx.x, b = blockIdx.y, tid = threadIdx.x;
    const int s0 = chunk * CROWS;
    uint32_t s_rows = (uint32_t)__cvta_generic_to_shared(rows);
    uint32_t s_we   = (uint32_t)__cvta_generic_to_shared(we);

    for (int i = tid; i < TWOH / 4; i += 256)
        cpa16(s_we + i * 16, (const float4*)(Wen + HH) + i);
    for (int i = tid; i < CROWS * (TWOH / 4); i += 256) {
        int r = i >> 9, c = i & 511;
        cpa16(s_rows + (r * (TWOH / 4) + c) * 16,
              (const float4*)(enc + ((size_t)(s0 + r) * BB + b) * TWOH) + c);
    }
    cpa_commit(); cpa_wait0();
    __syncthreads();

    const int w = tid >> 5, lane = tid & 31;
    const float hwb = g_hw[b], bev = be[0];
    {
        float p = 0.f;
        const float* row = rows + w * TWOH;
        for (int j = lane; j < TWOH; j += 32) p += row[j] * we[j];
        for (int o = 16; o; o >>= 1) p += __shfl_xor_sync(~0u, p, o);
        if (lane == 0) sE[w] = fmaxf(p + hwb + bev, 0.f);
    }
    __syncthreads();
    float m = -1e30f;
#pragma unroll
    for (int i = 0; i < CROWS; i++) m = fmaxf(m, sE[i]);
    float pe[CROWS]; float l = 0.f;
#pragma unroll
    for (int i = 0; i < CROWS; i++) { pe[i] = __expf(sE[i] - m); l += pe[i]; }
    float* dst = g_ctx + ((size_t)b * NCHUNK + chunk) * TWOH;
    for (int d = tid; d < TWOH; d += 256) {
        float v = 0.f;
#pragma unroll
        for (int i = 0; i < CROWS; i++) v += pe[i] * rows[i * TWOH + d];
        dst[d] = v;
    }
    if (tid == 0) { g_eM[b * NCHUNK + chunk] = m; g_eL[b * NCHUNK + chunk] = l; }
}

// ---------------- K2: combine -> rnn_in split bf16 [b][k] -------------------
__global__ void k_combine(const float* __restrict__ emb_table,
                          const int* __restrict__ x,
                          const float* __restrict__ hidden) {
    int b = blockIdx.x, tid = threadIdx.x;
    __shared__ float ssc[NCHUNK];
    __shared__ float sInv;
    if (tid == 0) {
        float M = -1e30f;
        for (int i = 0; i < NCHUNK; i++) M = fmaxf(M, g_eM[b * NCHUNK + i]);
        float L = 0.f;
        for (int i = 0; i < NCHUNK; i++) {
            float s = __expf(g_eM[b * NCHUNK + i] - M);
            ssc[i] = s;
            L += s * g_eL[b * NCHUNK + i];
        }
        sInv = 1.f / L;
    }
    __syncthreads();
    float inv = sInv;
    unsigned short hi, lo;
    for (int d = tid; d < TWOH; d += 256) {
        float v = 0.f;
#pragma unroll 8
        for (int i = 0; i < NCHUNK; i++)
            v += ssc[i] * g_ctx[((size_t)b * NCHUNK + i) * TWOH + d];
        split16(v * inv, hi, lo);
        g_Bhi[b * KTOT + d] = hi; g_Blo[b * KTOT + d] = lo;
    }
    int xb = x[b];
    for (int j = tid; j < EE; j += 256) {
        split16(emb_table[(size_t)xb * EE + j], hi, lo);
        g_Bhi[b * KTOT + TWOH + j] = hi; g_Blo[b * KTOT + TWOH + j] = lo;
    }
    for (int j = tid; j < HH; j += 256) {
        split16(hidden[b * HH + j], hi, lo);
        g_Bhi[b * KTOT + TWOH + EE + j] = hi; g_Blo[b * KTOT + TWOH + EE + j] = lo;
    }
}

// ================= HMMA GEMM pieces ==========================================
// convert prefetched fp32 A regs (8 float4 = half row of 64k) -> bf16 hi/lo smem
__device__ __forceinline__ void stsA_conv(uint32_t sb, const float4* pa, int cm, int ck) {
    uint32_t h[16], lw[16];
#pragma unroll
    for (int i = 0; i < 8; i++) {
        uint32_t bx = __float_as_uint(pa[i].x), by = __float_as_uint(pa[i].y);
        uint32_t bz = __float_as_uint(pa[i].z), bw = __float_as_uint(pa[i].w);
        h[2 * i]     = __byte_perm(bx, by, 0x7632);
        h[2 * i + 1] = __byte_perm(bz, bw, 0x7632);
        float lx = pa[i].x - __uint_as_float(bx & 0xFFFF0000u);
        float ly = pa[i].y - __uint_as_float(by & 0xFFFF0000u);
        float lz = pa[i].z - __uint_as_float(bz & 0xFFFF0000u);
        float lv = pa[i].w - __uint_as_float(bw & 0xFFFF0000u);
        lw[2 * i]     = __byte_perm(__float_as_uint(lx), __float_as_uint(ly), 0x7632);
        lw[2 * i + 1] = __byte_perm(__float_as_uint(lz), __float_as_uint(lv), 0x7632);
    }
    uint32_t d = sb + OFF_AHI + cm * ROWB + ck * 2;
#pragma unroll
    for (int q = 0; q < 4; q++) st4(d + q * 16, h[4 * q], h[4 * q + 1], h[4 * q + 2], h[4 * q + 3]);
    d = sb + OFF_ALO + cm * ROWB + ck * 2;
#pragma unroll
    for (int q = 0; q < 4; q++) st4(d + q * 16, lw[4 * q], lw[4 * q + 1], lw[4 * q + 2], lw[4 * q + 3]);
}

// warp MMA over one staged chunk: acc[8][4], A 16m x 64k, B 64n x 64k
__device__ __forceinline__ void domma(uint32_t sb, float (*acc)[4], int w, int l) {
    const int arow = w * 16 + (l & 7) + ((l >> 3) & 1) * 8;
    const int acol = ((l >> 4) & 1) * 8;
    const int brof = ((l >> 4) & 1) * 8 + (l & 7);
    const int bcol = ((l >> 3) & 1) * 8;
#pragma unroll
    for (int ks = 0; ks < 4; ks++) {
        uint32_t ahi[4], alo[4];
        uint32_t ao = arow * ROWB + (ks * 16 + acol) * 2;
        ldsm4(ahi, sb + OFF_AHI + ao);
        ldsm4(alo, sb + OFF_ALO + ao);
#pragma unroll
        for (int p = 0; p < 4; p++) {
            uint32_t bh[4], bl[4];
            uint32_t bo = (p * 16 + brof) * ROWB + (ks * 16 + bcol) * 2;
            ldsm4(bh, sb + OFF_BHI + bo);
            ldsm4(bl, sb + OFF_BLO + bo);
            mma16816(acc[2 * p],     ahi, bh);
            mma16816(acc[2 * p + 1], ahi, bh + 2);
            mma16816(acc[2 * p],     alo, bh);
            mma16816(acc[2 * p + 1], alo, bh + 2);
            mma16816(acc[2 * p],     ahi, bl);
            mma16816(acc[2 * p + 1], ahi, bl + 2);
        }
    }
}

// ---------------- K3: gates GEMM  grid(32, 7) --------------------------------
__global__ __launch_bounds__(256, 2)
void k_gates_mm(const float* __restrict__ Wih, const float* __restrict__ Whh) {
    extern __shared__ char dsm[];
    uint32_t base = (uint32_t)__cvta_generic_to_shared(dsm);
    const int tid = threadIdx.x, w = tid >> 5, l = tid & 31;
    const int mbase = blockIdx.x * MT;
    const int split = blockIdx.y;
    const int kstart = split * KSPLIT;
    const int NCH = KSPLIT / KC;     // 8

    const int cm = tid >> 1, ck = (tid & 1) * 32;     // A: row, k-half
    const int br0 = tid >> 3,          bc0 = (tid & 7) * 16;          // B idx tid
    const int br1 = (tid + 256) >> 3,  bc1 = ((tid + 256) & 7) * 16;  // B idx tid+256

    float acc[8][4];
#pragma unroll
    for (int i = 0; i < 8; i++)
#pragma unroll
        for (int j = 0; j < 4; j++) acc[i][j] = 0.f;

    float4 pa[8];
    auto ldgA = [&](int kg) {
        const float* src = (kg < 2560)
            ? Wih + (size_t)(mbase + cm) * 2560 + kg
            : Whh + (size_t)(mbase + cm) * 1024 + (kg - 2560);
#pragma unroll
        for (int i = 0; i < 8; i++) pa[i] = *(const float4*)(src + ck + i * 4);
    };
    auto cpaB = [&](int kg, uint32_t sb) {
        cpa16(sb + OFF_BHI + br0 * ROWB + bc0, (const char*)g_Bhi + (size_t)br0 * KTOT * 2 + kg * 2 + bc0);
        cpa16(sb + OFF_BHI + br1 * ROWB + bc1, (const char*)g_Bhi + (size_t)br1 * KTOT * 2 + kg * 2 + bc1);
        cpa16(sb + OFF_BLO + br0 * ROWB + bc0, (const char*)g_Blo + (size_t)br0 * KTOT * 2 + kg * 2 + bc0);
        cpa16(sb + OFF_BLO + br1 * ROWB + bc1, (const char*)g_Blo + (size_t)br1 * KTOT * 2 + kg * 2 + bc1);
        cpa_commit();
    };

    ldgA(kstart);
    cpaB(kstart, base);
    for (int c = 0; c < NCH; c++) {
        uint32_t sb = base + (c & 1) * STAGE;
        stsA_conv(sb, pa, cm, ck);
        cpa_wait0();
        __syncthreads();
        if (c + 1 < NCH) {
            int kg = kstart + (c + 1) * KC;
            ldgA(kg);
            cpaB(kg, base + ((c + 1) & 1) * STAGE);
        }
        domma(sb, acc, w, l);
        __syncthreads();
    }

    const int gid = l >> 2, tig = (l & 3) * 2;
    float* outp = g_gatesP + ((size_t)split * G4 + mbase + w * 16) * BB;
#pragma unroll
    for (int no = 0; no < 8; no++) {
        *(float2*)(outp + gid * BB + no * 8 + tig)       = make_float2(acc[no][0], acc[no][1]);
        *(float2*)(outp + (gid + 8) * BB + no * 8 + tig) = make_float2(acc[no][2], acc[no][3]);
    }
}

// ---------------- K3b: LSTM ---------------------------------------------------
__global__ void k_lstm(const float* __restrict__ b_ih, const float* __restrict__ b_hh,
                       const float* __restrict__ cell,
                       float* __restrict__ h1o, float* __restrict__ c1o) {
    int idx = blockIdx.x * blockDim.x + threadIdx.x;
    int b = idx & 63, j = idx >> 6;
    float gi = 0, gf = 0, gg = 0, go = 0;
#pragma unroll
    for (int s = 0; s < NSPLIT; s++) {
        const float* gp = g_gatesP + (size_t)s * G4 * BB;
        gi += gp[(j) * BB + b];
        gf += gp[(1024 + j) * BB + b];
        gg += gp[(2048 + j) * BB + b];
        go += gp[(3072 + j) * BB + b];
    }
    gi += b_ih[j]        + b_hh[j];
    gf += b_ih[1024 + j] + b_hh[1024 + j];
    gg += b_ih[2048 + j] + b_hh[2048 + j];
    go += b_ih[3072 + j] + b_hh[3072 + j];
    float c0 = cell[b * HH + j];
    float c1 = sigm(gf) * c0 + sigm(gi) * tanhf(gg);
    float h1 = sigm(go) * tanhf(c1);
    h1o[b * HH + j] = h1;
    c1o[b * HH + j] = c1;
    unsigned short hi, lo;
    split16(h1, hi, lo);
    g_h1hi[b * HH + j] = hi;
    g_h1lo[b * HH + j] = lo;
}

// ---------------- K4: FC GEMM  grid(250) --------------------------------------
__global__ __launch_bounds__(256, 2)
void k_fc_mm(const float* __restrict__ Wfc, const float* __restrict__ bfc,
             float* __restrict__ pred) {
    extern __shared__ char dsm[];
    uint32_t base = (uint32_t)__cvta_generic_to_shared(dsm);
    const int tid = threadIdx.x, w = tid >> 5, l = tid & 31;
    const int mbase = blockIdx.x * MT;
    const int NCH = HH / KC;         // 16

    const int cm = tid >> 1, ck = (tid & 1) * 32;
    const int br0 = tid >> 3,          bc0 = (tid & 7) * 16;
    const int br1 = (tid + 256) >> 3,  bc1 = ((tid + 256) & 7) * 16;

    float acc[8][4];
#pragma unroll
    for (int i = 0; i < 8; i++)
#pragma unroll
        for (int j = 0; j < 4; j++) acc[i][j] = 0.f;

    float4 pa[8];
    auto ldgA = [&](int kg) {
        const float* src = Wfc + (size_t)(mbase + cm) * HH + kg;
#pragma unroll
        for (int i = 0; i < 8; i++) pa[i] = *(const float4*)(src + ck + i * 4);
    };
    auto cpaB = [&](int kg, uint32_t sb) {
        cpa16(sb + OFF_BHI + br0 * ROWB + bc0, (const char*)g_h1hi + (size_t)br0 * HH * 2 + kg * 2 + bc0);
        cpa16(sb + OFF_BHI + br1 * ROWB + bc1, (const char*)g_h1hi + (size_t)br1 * HH * 2 + kg * 2 + bc1);
        cpa16(sb + OFF_BLO + br0 * ROWB + bc0, (const char*)g_h1lo + (size_t)br0 * HH * 2 + kg * 2 + bc0);
        cpa16(sb + OFF_BLO + br1 * ROWB + bc1, (const char*)g_h1lo + (size_t)br1 * HH * 2 + kg * 2 + bc1);
        cpa_commit();
    };

    ldgA(0);
    cpaB(0, base);
    for (int c = 0; c < NCH; c++) {
        uint32_t sb = base + (c & 1) * STAGE;
        stsA_conv(sb, pa, cm, ck);
        cpa_wait0();
        __syncthreads();
        if (c + 1 < NCH) {
            int kg = (c + 1) * KC;
            ldgA(kg);
            cpaB(kg, base + ((c + 1) & 1) * STAGE);
        }
        domma(sb, acc, w, l);
        __syncthreads();
    }

    // epilogue: transpose through smem, add bias, coalesced store
    float* ts = (float*)dsm;      // [64][132]
    const int gid = l >> 2, tig = (l & 3) * 2;
    float bias0 = bfc[mbase + w * 16 + gid];
    float bias1 = bfc[mbase + w * 16 + gid + 8];
#pragma unroll
    for (int no = 0; no < 8; no++) {
        int n = no * 8 + tig;
        ts[n * 132 + w * 16 + gid]           = acc[no][0] + bias0;
        ts[(n + 1) * 132 + w * 16 + gid]     = acc[no][1] + bias0;
        ts[n * 132 + w * 16 + gid + 8]       = acc[no][2] + bias1;
        ts[(n + 1) * 132 + w * 16 + gid + 8] = acc[no][3] + bias1;
    }
    __syncthreads();
    {
        int b = tid >> 2, q = tid & 3;
        const float* srow = ts + b * 132 + q * 32;
        float* drow = pred + (size_t)b * VV + mbase + q * 32;
#pragma unroll
        for (int i = 0; i < 8; i++)
            *(float4*)(drow + i * 4) = make_float4(srow[i * 4], srow[i * 4 + 1],
                                                   srow[i * 4 + 2], srow[i * 4 + 3]);
    }
}

// ---------------- launch --------------------------------------------------------
extern "C" void kernel_launch(void* const* d_in, const int* in_sizes, int n_in,
                              void* d_out, int out_size) {
    const int*   x       = (const int*)  d_in[0];
    const float* enc     = (const float*)d_in[1];
    const float* hidden  = (const float*)d_in[2];
    const float* cell    = (const float*)d_in[3];
    const float* emb     = (const float*)d_in[4];
    const float* Wen     = (const float*)d_in[5];
    const float* be      = (const float*)d_in[6];
    const float* Wih     = (const float*)d_in[7];
    const float* Whh     = (const float*)d_in[8];
    const float* b_ih    = (const float*)d_in[9];
    const float* b_hh    = (const float*)d_in[10];
    const float* Wfc     = (const float*)d_in[11];
    const float* bfc     = (const float*)d_in[12];

    float* pred = (float*)d_out;
    float* h1o  = pred + (size_t)BB * VV;
    float* c1o  = h1o + (size_t)BB * HH;

    const int smem_attn = (CROWS * TWOH + TWOH) * sizeof(float);   // 72 KB
    const int smem_gemm = 2 * STAGE;                               // 110592
    cudaFuncSetAttribute(k_attn, cudaFuncAttributeMaxDynamicSharedMemorySize, smem_attn);
    cudaFuncSetAttribute(k_gates_mm, cudaFuncAttributeMaxDynamicSharedMemorySize, smem_gemm);
    cudaFuncSetAttribute(k_fc_mm, cudaFuncAttributeMaxDynamicSharedMemorySize, smem_gemm);

    k_hw<<<BB, 128>>>(hidden, Wen);
    k_attn<<<dim3(NCHUNK, BB), 256, smem_attn>>>(enc, Wen, be);
    k_combine<<<BB, 256>>>(emb, x, hidden);
    k_gates_mm<<<dim3(G4 / MT, NSPLIT), 256, smem_gemm>>>(Wih, Whh);
    k_lstm<<<(BB * HH) / 256, 256>>>(b_ih, b_hh, cell, h1o, c1o);
    k_fc_mm<<<VV / MT, 256, smem_gemm>>>(Wfc, bfc, pred);
}

// round 9
// speedup vs baseline: 1.1356x; 1.1356x over previous
#include <cuda_runtime.h>
#include <cstdint>

#define SS 512
#define BB 64
#define HH 1024
#define EE 512
#define VV 32000
#define TWOH 2048
#define KTOT 3584
#define G4 4096
#define NCHUNK 64
#define CROWS 8
#define NSPLIT 7
#define KSPLIT 512

// HMMA GEMM pipeline config (KC=32)
#define MT 128
#define KC 32
#define RAWST 18432         // 128 rows * 144B (fp32 tile, padded)
#define BST 10240           // 64 rows * 80B * 2 (hi+lo)
#define CONVROW 80          // bf16 conv row stride (5*16B: aligned + conflict-free)
#define OFF_RAW 0           // 3 stages * 18432 = 55296
#define OFF_B   55296       // 3 stages * 10240 = 30720
#define OFF_CV  86016       // conv buffer 20480
#define CVLO 10240          // 128*80
#define SMEM_GEMM 106496

// ---------------- scratch ----------------------------------------------------
__device__ float g_hw[BB];
__device__ float g_eM[BB * NCHUNK];
__device__ float g_eL[BB * NCHUNK];
__device__ float g_ctx[(size_t)BB * NCHUNK * TWOH];
__device__ unsigned short g_Bhi[BB * KTOT];
__device__ unsigned short g_Blo[BB * KTOT];
__device__ unsigned short g_h1hi[BB * HH];
__device__ unsigned short g_h1lo[BB * HH];
__device__ float g_gatesP[NSPLIT * G4 * BB];

__device__ __forceinline__ float sigm(float x) { return 1.f / (1.f + __expf(-x)); }

__device__ __forceinline__ void cpa16(uint32_t s, const void* g) {
    asm volatile("cp.async.cg.shared.global [%0], [%1], 16;" :: "r"(s), "l"(g));
}
__device__ __forceinline__ void cpa_commit() { asm volatile("cp.async.commit_group;"); }
__device__ __forceinline__ void cpa_wait0()  { asm volatile("cp.async.wait_group 0;"); }
__device__ __forceinline__ void cpa_wait2()  { asm volatile("cp.async.wait_group 2;"); }

__device__ __forceinline__ void ldsm4(uint32_t* r, uint32_t addr) {
    asm volatile("ldmatrix.sync.aligned.m8n8.x4.shared.b16 {%0,%1,%2,%3}, [%4];"
        : "=r"(r[0]), "=r"(r[1]), "=r"(r[2]), "=r"(r[3]) : "r"(addr));
}
__device__ __forceinline__ void mma16816(float* d, const uint32_t* a, const uint32_t* b) {
    asm volatile("mma.sync.aligned.m16n8k16.row.col.f32.bf16.bf16.f32 "
        "{%0,%1,%2,%3},{%4,%5,%6,%7},{%8,%9},{%0,%1,%2,%3};"
        : "+f"(d[0]), "+f"(d[1]), "+f"(d[2]), "+f"(d[3])
        : "r"(a[0]), "r"(a[1]), "r"(a[2]), "r"(a[3]), "r"(b[0]), "r"(b[1]));
}
__device__ __forceinline__ void st2(uint32_t a, uint32_t x, uint32_t y) {
    asm volatile("st.shared.v2.u32 [%0], {%1,%2};" :: "r"(a), "r"(x), "r"(y));
}

__device__ __forceinline__ void split16(float x, unsigned short& hi, unsigned short& lo) {
    uint32_t bx = __float_as_uint(x);
    hi = (unsigned short)(bx >> 16);
    float lf = x - __uint_as_float(bx & 0xFFFF0000u);
    lo = (unsigned short)(__float_as_uint(lf) >> 16);
}

// ---------------- K0 ----------------------------------------------------------
__global__ void k_hw(const float* __restrict__ hidden, const float* __restrict__ Wen) {
    int b = blockIdx.x, tid = threadIdx.x;
    float p = 0.f;
    for (int k = tid; k < HH; k += 128) p += hidden[b * HH + k] * Wen[k];
    __shared__ float red[128];
    red[tid] = p; __syncthreads();
    for (int o = 64; o >= 32; o >>= 1) { if (tid < o) red[tid] += red[tid + o]; __syncthreads(); }
    if (tid < 32) {
        float v = red[tid];
        for (int o = 16; o; o >>= 1) v += __shfl_xor_sync(~0u, v, o);
        if (tid == 0) g_hw[b] = v;
    }
}

// ---------------- K1: attention --------------------------------------------
__global__ __launch_bounds__(256)
void k_attn(const float* __restrict__ enc, const float* __restrict__ Wen,
            const float* __restrict__ be) {
    extern __shared__ float sm[];
    float* rows = sm;
    float* we   = sm + CROWS * TWOH;
    __shared__ float sE[CROWS];
    const int chunk = blockIdx.x, b = blockIdx.y, tid = threadIdx.x;
    const int s0 = chunk * CROWS;
    uint32_t s_rows = (uint32_t)__cvta_generic_to_shared(rows);
    uint32_t s_we   = (uint32_t)__cvta_generic_to_shared(we);

    for (int i = tid; i < TWOH / 4; i += 256)
        cpa16(s_we + i * 16, (const float4*)(Wen + HH) + i);
    for (int i = tid; i < CROWS * (TWOH / 4); i += 256) {
        int r = i >> 9, c = i & 511;
        cpa16(s_rows + (r * (TWOH / 4) + c) * 16,
              (const float4*)(enc + ((size_t)(s0 + r) * BB + b) * TWOH) + c);
    }
    cpa_commit(); cpa_wait0();
    __syncthreads();

    const int w = tid >> 5, lane = tid & 31;
    const float hwb = g_hw[b], bev = be[0];
    {
        float p = 0.f;
        const float* row = rows + w * TWOH;
        for (int j = lane; j < TWOH; j += 32) p += row[j] * we[j];
        for (int o = 16; o; o >>= 1) p += __shfl_xor_sync(~0u, p, o);
        if (lane == 0) sE[w] = fmaxf(p + hwb + bev, 0.f);
    }
    __syncthreads();
    float m = -1e30f;
#pragma unroll
    for (int i = 0; i < CROWS; i++) m = fmaxf(m, sE[i]);
    float pe[CROWS]; float l = 0.f;
#pragma unroll
    for (int i = 0; i < CROWS; i++) { pe[i] = __expf(sE[i] - m); l += pe[i]; }
    float* dst = g_ctx + ((size_t)b * NCHUNK + chunk) * TWOH;
    for (int d = tid; d < TWOH; d += 256) {
        float v = 0.f;
#pragma unroll
        for (int i = 0; i < CROWS; i++) v += pe[i] * rows[i * TWOH + d];
        dst[d] = v;
    }
    if (tid == 0) { g_eM[b * NCHUNK + chunk] = m; g_eL[b * NCHUNK + chunk] = l; }
}

// ---------------- K2: combine -> rnn_in split bf16 [b][k] -------------------
__global__ void k_combine(const float* __restrict__ emb_table,
                          const int* __restrict__ x,
                          const float* __restrict__ hidden) {
    int b = blockIdx.x, tid = threadIdx.x;
    __shared__ float ssc[NCHUNK];
    __shared__ float sInv;
    if (tid == 0) {
        float M = -1e30f;
        for (int i = 0; i < NCHUNK; i++) M = fmaxf(M, g_eM[b * NCHUNK + i]);
        float L = 0.f;
        for (int i = 0; i < NCHUNK; i++) {
            float s = __expf(g_eM[b * NCHUNK + i] - M);
            ssc[i] = s;
            L += s * g_eL[b * NCHUNK + i];
        }
        sInv = 1.f / L;
    }
    __syncthreads();
    float inv = sInv;
    unsigned short hi, lo;
    for (int d = tid; d < TWOH; d += 256) {
        float v = 0.f;
#pragma unroll 8
        for (int i = 0; i < NCHUNK; i++)
            v += ssc[i] * g_ctx[((size_t)b * NCHUNK + i) * TWOH + d];
        split16(v * inv, hi, lo);
        g_Bhi[b * KTOT + d] = hi; g_Blo[b * KTOT + d] = lo;
    }
    int xb = x[b];
    for (int j = tid; j < EE; j += 256) {
        split16(emb_table[(size_t)xb * EE + j], hi, lo);
        g_Bhi[b * KTOT + TWOH + j] = hi; g_Blo[b * KTOT + TWOH + j] = lo;
    }
    for (int j = tid; j < HH; j += 256) {
        split16(hidden[b * HH + j], hi, lo);
        g_Bhi[b * KTOT + TWOH + EE + j] = hi; g_Blo[b * KTOT + TWOH + EE + j] = lo;
    }
}

// ================= pipelined HMMA GEMM pieces =================================
// convert one staged raw fp32 tile (128x32, 144B rows) -> bf16 hi/lo (80B rows)
__device__ __forceinline__ void convert_tile(uint32_t raws, uint32_t convb, int tid) {
    const int row = tid >> 1, half = tid & 1;
    uint32_t src = raws + row * 144 + half * 64;
    float4 f[4];
#pragma unroll
    for (int i = 0; i < 4; i++) {
        asm volatile("ld.shared.v4.f32 {%0,%1,%2,%3}, [%4];"
            : "=f"(f[i].x), "=f"(f[i].y), "=f"(f[i].z), "=f"(f[i].w)
            : "r"(src + i * 16));
    }
    uint32_t h[8], lw[8];
#pragma unroll
    for (int i = 0; i < 4; i++) {
        uint32_t bx = __float_as_uint(f[i].x), by = __float_as_uint(f[i].y);
        uint32_t bz = __float_as_uint(f[i].z), bw = __float_as_uint(f[i].w);
        h[2 * i]     = __byte_perm(bx, by, 0x7632);
        h[2 * i + 1] = __byte_perm(bz, bw, 0x7632);
        float lx = f[i].x - __uint_as_float(bx & 0xFFFF0000u);
        float ly = f[i].y - __uint_as_float(by & 0xFFFF0000u);
        float lz = f[i].z - __uint_as_float(bz & 0xFFFF0000u);
        float lv = f[i].w - __uint_as_float(bw & 0xFFFF0000u);
        lw[2 * i]     = __byte_perm(__float_as_uint(lx), __float_as_uint(ly), 0x7632);
        lw[2 * i + 1] = __byte_perm(__float_as_uint(lz), __float_as_uint(lv), 0x7632);
    }
    uint32_t dh = convb + row * CONVROW + half * 32;
    uint32_t dl = dh + CVLO;
#pragma unroll
    for (int q = 0; q < 4; q++) st2(dh + q * 8, h[2 * q], h[2 * q + 1]);
#pragma unroll
    for (int q = 0; q < 4; q++) st2(dl + q * 8, lw[2 * q], lw[2 * q + 1]);
}

// warp MMA over one chunk: A (conv, 80B rows), B (stage, 80B rows)
__device__ __forceinline__ void domma(uint32_t convb, uint32_t bst, float (*acc)[4],
                                      int w, int l) {
    const int arow = w * 16 + (l & 7) + ((l >> 3) & 1) * 8;
    const int acol = ((l >> 4) & 1) * 8;
    const int brof = ((l >> 4) & 1) * 8 + (l & 7);
    const int bcol = ((l >> 3) & 1) * 8;
#pragma unroll
    for (int ks = 0; ks < 2; ks++) {
        uint32_t ahi[4], alo[4];
        uint32_t ao = arow * CONVROW + (ks * 16 + acol) * 2;
        ldsm4(ahi, convb + ao);
        ldsm4(alo, convb + CVLO + ao);
#pragma unroll
        for (int p = 0; p < 4; p++) {
            uint32_t bh[4], bl[4];
            uint32_t bo = (p * 16 + brof) * 80 + (ks * 16 + bcol) * 2;
            ldsm4(bh, bst + bo);
            ldsm4(bl, bst + 5120 + bo);
            mma16816(acc[2 * p],     ahi, bh);
            mma16816(acc[2 * p + 1], ahi, bh + 2);
            mma16816(acc[2 * p],     alo, bh);
            mma16816(acc[2 * p + 1], alo, bh + 2);
            mma16816(acc[2 * p],     ahi, bl);
            mma16816(acc[2 * p + 1], ahi, bl + 2);
        }
    }
}

// ---------------- K3: gates GEMM  grid(32, 7) --------------------------------
__global__ __launch_bounds__(256, 2)
void k_gates_mm(const float* __restrict__ Wih, const float* __restrict__ Whh) {
    extern __shared__ char dsm[];
    uint32_t base = (uint32_t)__cvta_generic_to_shared(dsm);
    const int tid = threadIdx.x, w = tid >> 5, l = tid & 31;
    const int mbase = blockIdx.x * MT;
    const int split = blockIdx.y;
    const int kstart = split * KSPLIT;
    const int NCH = KSPLIT / KC;     // 16

    const int row = tid >> 1, half = tid & 1;      // A copy coords
    const int br = tid >> 2, bo = (tid & 3) * 16;  // B copy coords

    float acc[8][4];
#pragma unroll
    for (int i = 0; i < 8; i++)
#pragma unroll
        for (int j = 0; j < 4; j++) acc[i][j] = 0.f;

    auto issue = [&](int c) {
        int kg = kstart + c * KC;
        uint32_t rs = base + OFF_RAW + (c % 3) * RAWST + row * 144 + half * 64;
        const float* src = (kg < 2560)
            ? Wih + (size_t)(mbase + row) * 2560 + kg
            : Whh + (size_t)(mbase + row) * 1024 + (kg - 2560);
        src += half * 16;
#pragma unroll
        for (int i = 0; i < 4; i++) cpa16(rs + i * 16, src + i * 4);
        uint32_t bs = base + OFF_B + (c % 3) * BST;
        cpa16(bs + br * 80 + bo,        (const char*)g_Bhi + (size_t)br * KTOT * 2 + kg * 2 + bo);
        cpa16(bs + 5120 + br * 80 + bo, (const char*)g_Blo + (size_t)br * KTOT * 2 + kg * 2 + bo);
        cpa_commit();
    };

    issue(0); issue(1); issue(2);
    uint32_t convb = base + OFF_CV;
    for (int c = 0; c < NCH; c++) {
        cpa_wait2();
        __syncthreads();
        convert_tile(base + OFF_RAW + (c % 3) * RAWST, convb, tid);
        __syncthreads();
        domma(convb, base + OFF_B + (c % 3) * BST, acc, w, l);
        if (c + 3 < NCH) {
            __syncthreads();            // all reads of stage (c%3) complete
            issue(c + 3);               // now safe to overwrite raw/B stage (c%3)
        }
    }

    const int gid = l >> 2, tig = (l & 3) * 2;
    float* outp = g_gatesP + ((size_t)split * G4 + mbase + w * 16) * BB;
#pragma unroll
    for (int no = 0; no < 8; no++) {
        *(float2*)(outp + gid * BB + no * 8 + tig)       = make_float2(acc[no][0], acc[no][1]);
        *(float2*)(outp + (gid + 8) * BB + no * 8 + tig) = make_float2(acc[no][2], acc[no][3]);
    }
}

// ---------------- K3b: LSTM ---------------------------------------------------
__global__ void k_lstm(const float* __restrict__ b_ih, const float* __restrict__ b_hh,
                       const float* __restrict__ cell,
                       float* __restrict__ h1o, float* __restrict__ c1o) {
    int idx = blockIdx.x * blockDim.x + threadIdx.x;
    int b = idx & 63, j = idx >> 6;
    float gi = 0, gf = 0, gg = 0, go = 0;
#pragma unroll
    for (int s = 0; s < NSPLIT; s++) {
        const float* gp = g_gatesP + (size_t)s * G4 * BB;
        gi += gp[(j) * BB + b];
        gf += gp[(1024 + j) * BB + b];
        gg += gp[(2048 + j) * BB + b];
        go += gp[(3072 + j) * BB + b];
    }
    gi += b_ih[j]        + b_hh[j];
    gf += b_ih[1024 + j] + b_hh[1024 + j];
    gg += b_ih[2048 + j] + b_hh[2048 + j];
    go += b_ih[3072 + j] + b_hh[3072 + j];
    float c0 = cell[b * HH + j];
    float c1 = sigm(gf) * c0 + sigm(gi) * tanhf(gg);
    float h1 = sigm(go) * tanhf(c1);
    h1o[b * HH + j] = h1;
    c1o[b * HH + j] = c1;
    unsigned short hi, lo;
    split16(h1, hi, lo);
    g_h1hi[b * HH + j] = hi;
    g_h1lo[b * HH + j] = lo;
}

// ---------------- K4: FC GEMM  grid(250) --------------------------------------
__global__ __launch_bounds__(256, 2)
void k_fc_mm(const float* __restrict__ Wfc, const float* __restrict__ bfc,
             float* __restrict__ pred) {
    extern __shared__ char dsm[];
    uint32_t base = (uint32_t)__cvta_generic_to_shared(dsm);
    const int tid = threadIdx.x, w = tid >> 5, l = tid & 31;
    const int mbase = blockIdx.x * MT;
    const int NCH = HH / KC;         // 32

    const int row = tid >> 1, half = tid & 1;
    const int br = tid >> 2, bo = (tid & 3) * 16;

    float acc[8][4];
#pragma unroll
    for (int i = 0; i < 8; i++)
#pragma unroll
        for (int j = 0; j < 4; j++) acc[i][j] = 0.f;

    auto issue = [&](int c) {
        int kg = c * KC;
        uint32_t rs = base + OFF_RAW + (c % 3) * RAWST + row * 144 + half * 64;
        const float* src = Wfc + (size_t)(mbase + row) * HH + kg + half * 16;
#pragma unroll
        for (int i = 0; i < 4; i++) cpa16(rs + i * 16, src + i * 4);
        uint32_t bs = base + OFF_B + (c % 3) * BST;
        cpa16(bs + br * 80 + bo,        (const char*)g_h1hi + (size_t)br * HH * 2 + kg * 2 + bo);
        cpa16(bs + 5120 + br * 80 + bo, (const char*)g_h1lo + (size_t)br * HH * 2 + kg * 2 + bo);
        cpa_commit();
    };

    issue(0); issue(1); issue(2);
    uint32_t convb = base + OFF_CV;
    for (int c = 0; c < NCH; c++) {
        cpa_wait2();
        __syncthreads();
        convert_tile(base + OFF_RAW + (c % 3) * RAWST, convb, tid);
        __syncthreads();
        domma(convb, base + OFF_B + (c % 3) * BST, acc, w, l);
        if (c + 3 < NCH) {
            __syncthreads();
            issue(c + 3);
        }
    }
    __syncthreads();

    // epilogue: transpose through smem, add bias, coalesced store
    float* ts = (float*)dsm;      // [64][132]
    const int gid = l >> 2, tig = (l & 3) * 2;
    float bias0 = bfc[mbase + w * 16 + gid];
    float bias1 = bfc[mbase + w * 16 + gid + 8];
#pragma unroll
    for (int no = 0; no < 8; no++) {
        int n = no * 8 + tig;
        ts[n * 132 + w * 16 + gid]           = acc[no][0] + bias0;
        ts[(n + 1) * 132 + w * 16 + gid]     = acc[no][1] + bias0;
        ts[n * 132 + w * 16 + gid + 8]       = acc[no][2] + bias1;
        ts[(n + 1) * 132 + w * 16 + gid + 8] = acc[no][3] + bias1;
    }
    __syncthreads();
    {
        int b = tid >> 2, q = tid & 3;
        const float* srow = ts + b * 132 + q * 32;
        float* drow = pred + (size_t)b * VV + mbase + q * 32;
#pragma unroll
        for (int i = 0; i < 8; i++)
            *(float4*)(drow + i * 4) = make_float4(srow[i * 4], srow[i * 4 + 1],
                                                   srow[i * 4 + 2], srow[i * 4 + 3]);
    }
}

// ---------------- launch --------------------------------------------------------
extern "C" void kernel_launch(void* const* d_in, const int* in_sizes, int n_in,
                              void* d_out, int out_size) {
    const int*   x       = (const int*)  d_in[0];
    const float* enc     = (const float*)d_in[1];
    const float* hidden  = (const float*)d_in[2];
    const float* cell    = (const float*)d_in[3];
    const float* emb     = (const float*)d_in[4];
    const float* Wen     = (const float*)d_in[5];
    const float* be      = (const float*)d_in[6];
    const float* Wih     = (const float*)d_in[7];
    const float* Whh     = (const float*)d_in[8];
    const float* b_ih    = (const float*)d_in[9];
    const float* b_hh    = (const float*)d_in[10];
    const float* Wfc     = (const float*)d_in[11];
    const float* bfc     = (const float*)d_in[12];

    float* pred = (float*)d_out;
    float* h1o  = pred + (size_t)BB * VV;
    float* c1o  = h1o + (size_t)BB * HH;

    const int smem_attn = (CROWS * TWOH + TWOH) * sizeof(float);   // 72 KB
    cudaFuncSetAttribute(k_attn, cudaFuncAttributeMaxDynamicSharedMemorySize, smem_attn);
    cudaFuncSetAttribute(k_gates_mm, cudaFuncAttributeMaxDynamicSharedMemorySize, SMEM_GEMM);
    cudaFuncSetAttribute(k_fc_mm, cudaFuncAttributeMaxDynamicSharedMemorySize, SMEM_GEMM);

    k_hw<<<BB, 128>>>(hidden, Wen);
    k_attn<<<dim3(NCHUNK, BB), 256, smem_attn>>>(enc, Wen, be);
    k_combine<<<BB, 256>>>(emb, x, hidden);
    k_gates_mm<<<dim3(G4 / MT, NSPLIT), 256, SMEM_GEMM>>>(Wih, Whh);
    k_lstm<<<(BB * HH) / 256, 256>>>(b_ih, b_hh, cell, h1o, c1o);
    k_fc_mm<<<VV / MT, 256, SMEM_GEMM>>>(Wfc, bfc, pred);
}

// round 10
// speedup vs baseline: 1.2537x; 1.1040x over previous
#include <cuda_runtime.h>
#include <cstdint>

#define SS 512
#define BB 64
#define HH 1024
#define EE 512
#define VV 32000
#define TWOH 2048
#define KTOT 3584
#define G4 4096
#define NCHUNK 64
#define CROWS 8
#define NSPLIT 14
#define KSPLIT 256

// HMMA GEMM tile config (R5-proven structure)
#define MT 128              // m rows per CTA (weight rows)
#define KC 32               // k per chunk
#define OFF_AHI 0
#define OFF_ALO 10240       // 128*80
#define OFF_BHI 20480
#define OFF_BLO 25600
#define STAGE 30720

// ---------------- scratch ----------------------------------------------------
__device__ float g_hw[BB];
__device__ float g_eM[BB * NCHUNK];
__device__ float g_eL[BB * NCHUNK];
__device__ float g_ctx[(size_t)BB * NCHUNK * TWOH];
__device__ unsigned short g_Bhi[BB * KTOT];   // rnn_in bf16 hi  [b][k]
__device__ unsigned short g_Blo[BB * KTOT];
__device__ unsigned short g_h1hi[BB * HH];
__device__ unsigned short g_h1lo[BB * HH];
__device__ float g_gatesP[NSPLIT * G4 * BB];  // [s][m][b]

__device__ __forceinline__ float sigm(float x) { return 1.f / (1.f + __expf(-x)); }

__device__ __forceinline__ void cpa16(uint32_t s, const void* g) {
    asm volatile("cp.async.cg.shared.global [%0], [%1], 16;" :: "r"(s), "l"(g));
}
__device__ __forceinline__ void cpa_commit() { asm volatile("cp.async.commit_group;"); }
__device__ __forceinline__ void cpa_wait0()  { asm volatile("cp.async.wait_group 0;"); }

__device__ __forceinline__ void ldsm4(uint32_t* r, uint32_t addr) {
    asm volatile("ldmatrix.sync.aligned.m8n8.x4.shared.b16 {%0,%1,%2,%3}, [%4];"
        : "=r"(r[0]), "=r"(r[1]), "=r"(r[2]), "=r"(r[3]) : "r"(addr));
}
__device__ __forceinline__ void mma16816(float* d, const uint32_t* a, const uint32_t* b) {
    asm volatile("mma.sync.aligned.m16n8k16.row.col.f32.bf16.bf16.f32 "
        "{%0,%1,%2,%3},{%4,%5,%6,%7},{%8,%9},{%0,%1,%2,%3};"
        : "+f"(d[0]), "+f"(d[1]), "+f"(d[2]), "+f"(d[3])
        : "r"(a[0]), "r"(a[1]), "r"(a[2]), "r"(a[3]), "r"(b[0]), "r"(b[1]));
}
__device__ __forceinline__ void st4(uint32_t a, uint32_t x, uint32_t y, uint32_t z, uint32_t w) {
    asm volatile("st.shared.v4.u32 [%0], {%1,%2,%3,%4};" :: "r"(a), "r"(x), "r"(y), "r"(z), "r"(w));
}

__device__ __forceinline__ void split16(float x, unsigned short& hi, unsigned short& lo) {
    uint32_t bx = __float_as_uint(x);
    hi = (unsigned short)(bx >> 16);
    float lf = x - __uint_as_float(bx & 0xFFFF0000u);
    lo = (unsigned short)(__float_as_uint(lf) >> 16);
}

// ---------------- K0 ----------------------------------------------------------
__global__ void k_hw(const float* __restrict__ hidden, const float* __restrict__ Wen) {
    int b = blockIdx.x, tid = threadIdx.x;
    float p = 0.f;
    for (int k = tid; k < HH; k += 128) p += hidden[b * HH + k] * Wen[k];
    __shared__ float red[128];
    red[tid] = p; __syncthreads();
    for (int o = 64; o >= 32; o >>= 1) { if (tid < o) red[tid] += red[tid + o]; __syncthreads(); }
    if (tid < 32) {
        float v = red[tid];
        for (int o = 16; o; o >>= 1) v += __shfl_xor_sync(~0u, v, o);
        if (tid == 0) g_hw[b] = v;
    }
}

// ---------------- K1: attention --------------------------------------------
__global__ __launch_bounds__(256)
void k_attn(const float* __restrict__ enc, const float* __restrict__ Wen,
            const float* __restrict__ be) {
    extern __shared__ float sm[];
    float* rows = sm;
    float* we   = sm + CROWS * TWOH;
    __shared__ float sE[CROWS];
    const int chunk = blockIdx.x, b = blockIdx.y, tid = threadIdx.x;
    const int s0 = chunk * CROWS;
    uint32_t s_rows = (uint32_t)__cvta_generic_to_shared(rows);
    uint32_t s_we   = (uint32_t)__cvta_generic_to_shared(we);

    for (int i = tid; i < TWOH / 4; i += 256)
        cpa16(s_we + i * 16, (const float4*)(Wen + HH) + i);
    for (int i = tid; i < CROWS * (TWOH / 4); i += 256) {
        int r = i >> 9, c = i & 511;
        cpa16(s_rows + (r * (TWOH / 4) + c) * 16,
              (const float4*)(enc + ((size_t)(s0 + r) * BB + b) * TWOH) + c);
    }
    cpa_commit(); cpa_wait0();
    __syncthreads();

    const int w = tid >> 5, lane = tid & 31;
    const float hwb = g_hw[b], bev = be[0];
    {
        float p = 0.f;
        const float* row = rows + w * TWOH;
        for (int j = lane; j < TWOH; j += 32) p += row[j] * we[j];
        for (int o = 16; o; o >>= 1) p += __shfl_xor_sync(~0u, p, o);
        if (lane == 0) sE[w] = fmaxf(p + hwb + bev, 0.f);
    }
    __syncthreads();
    float m = -1e30f;
#pragma unroll
    for (int i = 0; i < CROWS; i++) m = fmaxf(m, sE[i]);
    float pe[CROWS]; float l = 0.f;
#pragma unroll
    for (int i = 0; i < CROWS; i++) { pe[i] = __expf(sE[i] - m); l += pe[i]; }
    float* dst = g_ctx + ((size_t)b * NCHUNK + chunk) * TWOH;
    for (int d = tid; d < TWOH; d += 256) {
        float v = 0.f;
#pragma unroll
        for (int i = 0; i < CROWS; i++) v += pe[i] * rows[i * TWOH + d];
        dst[d] = v;
    }
    if (tid == 0) { g_eM[b * NCHUNK + chunk] = m; g_eL[b * NCHUNK + chunk] = l; }
}

// ---------------- K2: combine -> rnn_in split bf16 [b][k] -------------------
__global__ void k_combine(const float* __restrict__ emb_table,
                          const int* __restrict__ x,
                          const float* __restrict__ hidden) {
    int b = blockIdx.x, tid = threadIdx.x;
    __shared__ float ssc[NCHUNK];
    __shared__ float sInv;
    if (tid == 0) {
        float M = -1e30f;
        for (int i = 0; i < NCHUNK; i++) M = fmaxf(M, g_eM[b * NCHUNK + i]);
        float L = 0.f;
        for (int i = 0; i < NCHUNK; i++) {
            float s = __expf(g_eM[b * NCHUNK + i] - M);
            ssc[i] = s;
            L += s * g_eL[b * NCHUNK + i];
        }
        sInv = 1.f / L;
    }
    __syncthreads();
    float inv = sInv;
    unsigned short hi, lo;
    for (int d = tid; d < TWOH; d += 256) {
        float v = 0.f;
#pragma unroll 8
        for (int i = 0; i < NCHUNK; i++)
            v += ssc[i] * g_ctx[((size_t)b * NCHUNK + i) * TWOH + d];
        split16(v * inv, hi, lo);
        g_Bhi[b * KTOT + d] = hi; g_Blo[b * KTOT + d] = lo;
    }
    int xb = x[b];
    for (int j = tid; j < EE; j += 256) {
        split16(emb_table[(size_t)xb * EE + j], hi, lo);
        g_Bhi[b * KTOT + TWOH + j] = hi; g_Blo[b * KTOT + TWOH + j] = lo;
    }
    for (int j = tid; j < HH; j += 256) {
        split16(hidden[b * HH + j], hi, lo);
        g_Bhi[b * KTOT + TWOH + EE + j] = hi; g_Blo[b * KTOT + TWOH + EE + j] = lo;
    }
}

// ================= HMMA GEMM pieces (R5 structure) ============================
// convert prefetched fp32 A regs -> bf16 hi/lo smem tiles (80B rows)
__device__ __forceinline__ void stsA_conv(uint32_t sb, const float4* pa, int cm, int ckq) {
    uint32_t h[8], lw[8];
#pragma unroll
    for (int i = 0; i < 4; i++) {
        uint32_t bx = __float_as_uint(pa[i].x), by = __float_as_uint(pa[i].y);
        uint32_t bz = __float_as_uint(pa[i].z), bw = __float_as_uint(pa[i].w);
        h[2 * i]     = __byte_perm(bx, by, 0x7632);
        h[2 * i + 1] = __byte_perm(bz, bw, 0x7632);
        float lx = pa[i].x - __uint_as_float(bx & 0xFFFF0000u);
        float ly = pa[i].y - __uint_as_float(by & 0xFFFF0000u);
        float lz = pa[i].z - __uint_as_float(bz & 0xFFFF0000u);
        float lv = pa[i].w - __uint_as_float(bw & 0xFFFF0000u);
        lw[2 * i]     = __byte_perm(__float_as_uint(lx), __float_as_uint(ly), 0x7632);
        lw[2 * i + 1] = __byte_perm(__float_as_uint(lz), __float_as_uint(lv), 0x7632);
    }
    uint32_t d = sb + OFF_AHI + cm * 80 + ckq * 2;
    st4(d, h[0], h[1], h[2], h[3]);
    st4(d + 16, h[4], h[5], h[6], h[7]);
    d = sb + OFF_ALO + cm * 80 + ckq * 2;
    st4(d, lw[0], lw[1], lw[2], lw[3]);
    st4(d + 16, lw[4], lw[5], lw[6], lw[7]);
}

// warp MMA over one staged chunk: acc[8][4], A 16m x 32k, B 64n x 32k
__device__ __forceinline__ void domma(uint32_t sb, float (*acc)[4], int w, int l) {
    const int arow = w * 16 + (l & 7) + ((l >> 3) & 1) * 8;
    const int acol = ((l >> 4) & 1) * 8;
    const int brof = ((l >> 4) & 1) * 8 + (l & 7);
    const int bcol = ((l >> 3) & 1) * 8;
#pragma unroll
    for (int ks = 0; ks < 2; ks++) {
        uint32_t ahi[4], alo[4];
        uint32_t ao = arow * 80 + (ks * 16 + acol) * 2;
        ldsm4(ahi, sb + OFF_AHI + ao);
        ldsm4(alo, sb + OFF_ALO + ao);
#pragma unroll
        for (int p = 0; p < 4; p++) {
            uint32_t bh[4], bl[4];
            uint32_t bo = (p * 16 + brof) * 80 + (ks * 16 + bcol) * 2;
            ldsm4(bh, sb + OFF_BHI + bo);
            ldsm4(bl, sb + OFF_BLO + bo);
            mma16816(acc[2 * p],     ahi, bh);
            mma16816(acc[2 * p + 1], ahi, bh + 2);
            mma16816(acc[2 * p],     alo, bh);
            mma16816(acc[2 * p + 1], alo, bh + 2);
            mma16816(acc[2 * p],     ahi, bl);
            mma16816(acc[2 * p + 1], ahi, bl + 2);
        }
    }
}

// ---------------- K3: gates GEMM  grid(32, 14) --------------------------------
__global__ __launch_bounds__(256, 3)
void k_gates_mm(const float* __restrict__ Wih, const float* __restrict__ Whh) {
    extern __shared__ char dsm[];
    uint32_t base = (uint32_t)__cvta_generic_to_shared(dsm);
    const int tid = threadIdx.x, w = tid >> 5, l = tid & 31;
    const int mbase = blockIdx.x * MT;
    const int split = blockIdx.y;
    const int kstart = split * KSPLIT;
    const int NCH = KSPLIT / KC;     // 8

    const int cm = tid >> 1, ckq = (tid & 1) * 16;
    const int bn = tid >> 2, bq = (tid & 3) * 16;

    float acc[8][4];
#pragma unroll
    for (int i = 0; i < 8; i++)
#pragma unroll
        for (int j = 0; j < 4; j++) acc[i][j] = 0.f;

    float4 pa[4];
    auto ldgA = [&](int kg) {
        const float* src = (kg < 2560)
            ? Wih + (size_t)(mbase + cm) * 2560 + kg
            : Whh + (size_t)(mbase + cm) * 1024 + (kg - 2560);
#pragma unroll
        for (int i = 0; i < 4; i++) pa[i] = *(const float4*)(src + ckq + i * 4);
    };
    auto cpaB = [&](int kg, uint32_t sb) {
        cpa16(sb + OFF_BHI + bn * 80 + bq, (const char*)g_Bhi + (size_t)bn * KTOT * 2 + kg * 2 + bq);
        cpa16(sb + OFF_BLO + bn * 80 + bq, (const char*)g_Blo + (size_t)bn * KTOT * 2 + kg * 2 + bq);
        cpa_commit();
    };

    ldgA(kstart);
    cpaB(kstart, base);
    for (int c = 0; c < NCH; c++) {
        uint32_t sb = base + (c & 1) * STAGE;
        stsA_conv(sb, pa, cm, ckq);
        cpa_wait0();
        __syncthreads();
        if (c + 1 < NCH) {
            int kg = kstart + (c + 1) * KC;
            ldgA(kg);
            cpaB(kg, base + ((c + 1) & 1) * STAGE);
        }
        domma(sb, acc, w, l);
        __syncthreads();
    }

    const int gid = l >> 2, tig = (l & 3) * 2;
    float* outp = g_gatesP + ((size_t)split * G4 + mbase + w * 16) * BB;
#pragma unroll
    for (int no = 0; no < 8; no++) {
        *(float2*)(outp + gid * BB + no * 8 + tig)       = make_float2(acc[no][0], acc[no][1]);
        *(float2*)(outp + (gid + 8) * BB + no * 8 + tig) = make_float2(acc[no][2], acc[no][3]);
    }
}

// ---------------- K3b: LSTM ---------------------------------------------------
__global__ void k_lstm(const float* __restrict__ b_ih, const float* __restrict__ b_hh,
                       const float* __restrict__ cell,
                       float* __restrict__ h1o, float* __restrict__ c1o) {
    int idx = blockIdx.x * blockDim.x + threadIdx.x;
    int b = idx & 63, j = idx >> 6;
    float gi = 0, gf = 0, gg = 0, go = 0;
#pragma unroll
    for (int s = 0; s < NSPLIT; s++) {
        const float* gp = g_gatesP + (size_t)s * G4 * BB;
        gi += gp[(j) * BB + b];
        gf += gp[(1024 + j) * BB + b];
        gg += gp[(2048 + j) * BB + b];
        go += gp[(3072 + j) * BB + b];
    }
    gi += b_ih[j]        + b_hh[j];
    gf += b_ih[1024 + j] + b_hh[1024 + j];
    gg += b_ih[2048 + j] + b_hh[2048 + j];
    go += b_ih[3072 + j] + b_hh[3072 + j];
    float c0 = cell[b * HH + j];
    float c1 = sigm(gf) * c0 + sigm(gi) * tanhf(gg);
    float h1 = sigm(go) * tanhf(c1);
    h1o[b * HH + j] = h1;
    c1o[b * HH + j] = c1;
    unsigned short hi, lo;
    split16(h1, hi, lo);
    g_h1hi[b * HH + j] = hi;
    g_h1lo[b * HH + j] = lo;
}

// ---------------- K4: FC GEMM  grid(250) --------------------------------------
__global__ __launch_bounds__(256, 3)
void k_fc_mm(const float* __restrict__ Wfc, const float* __restrict__ bfc,
             float* __restrict__ pred) {
    extern __shared__ char dsm[];
    uint32_t base = (uint32_t)__cvta_generic_to_shared(dsm);
    const int tid = threadIdx.x, w = tid >> 5, l = tid & 31;
    const int mbase = blockIdx.x * MT;
    const int NCH = HH / KC;         // 32

    const int cm = tid >> 1, ckq = (tid & 1) * 16;
    const int bn = tid >> 2, bq = (tid & 3) * 16;

    float acc[8][4];
#pragma unroll
    for (int i = 0; i < 8; i++)
#pragma unroll
        for (int j = 0; j < 4; j++) acc[i][j] = 0.f;

    float4 pa[4];
    auto ldgA = [&](int kg) {
        const float* src = Wfc + (size_t)(mbase + cm) * HH + kg;
#pragma unroll
        for (int i = 0; i < 4; i++) pa[i] = *(const float4*)(src + ckq + i * 4);
    };
    auto cpaB = [&](int kg, uint32_t sb) {
        cpa16(sb + OFF_BHI + bn * 80 + bq, (const char*)g_h1hi + (size_t)bn * HH * 2 + kg * 2 + bq);
        cpa16(sb + OFF_BLO + bn * 80 + bq, (const char*)g_h1lo + (size_t)bn * HH * 2 + kg * 2 + bq);
        cpa_commit();
    };

    ldgA(0);
    cpaB(0, base);
    for (int c = 0; c < NCH; c++) {
        uint32_t sb = base + (c & 1) * STAGE;
        stsA_conv(sb, pa, cm, ckq);
        cpa_wait0();
        __syncthreads();
        if (c + 1 < NCH) {
            int kg = (c + 1) * KC;
            ldgA(kg);
            cpaB(kg, base + ((c + 1) & 1) * STAGE);
        }
        domma(sb, acc, w, l);
        __syncthreads();
    }

    // epilogue: transpose through smem, add bias, coalesced store
    float* ts = (float*)dsm;      // [64][132]
    const int gid = l >> 2, tig = (l & 3) * 2;
    float bias0 = bfc[mbase + w * 16 + gid];
    float bias1 = bfc[mbase + w * 16 + gid + 8];
#pragma unroll
    for (int no = 0; no < 8; no++) {
        int n = no * 8 + tig;
        ts[n * 132 + w * 16 + gid]           = acc[no][0] + bias0;
        ts[(n + 1) * 132 + w * 16 + gid]     = acc[no][1] + bias0;
        ts[n * 132 + w * 16 + gid + 8]       = acc[no][2] + bias1;
        ts[(n + 1) * 132 + w * 16 + gid + 8] = acc[no][3] + bias1;
    }
    __syncthreads();
    {
        int b = tid >> 2, q = tid & 3;
        const float* srow = ts + b * 132 + q * 32;
        float* drow = pred + (size_t)b * VV + mbase + q * 32;
#pragma unroll
        for (int i = 0; i < 8; i++)
            *(float4*)(drow + i * 4) = make_float4(srow[i * 4], srow[i * 4 + 1],
                                                   srow[i * 4 + 2], srow[i * 4 + 3]);
    }
}

// ---------------- launch --------------------------------------------------------
extern "C" void kernel_launch(void* const* d_in, const int* in_sizes, int n_in,
                              void* d_out, int out_size) {
    const int*   x       = (const int*)  d_in[0];
    const float* enc     = (const float*)d_in[1];
    const float* hidden  = (const float*)d_in[2];
    const float* cell    = (const float*)d_in[3];
    const float* emb     = (const float*)d_in[4];
    const float* Wen     = (const float*)d_in[5];
    const float* be      = (const float*)d_in[6];
    const float* Wih     = (const float*)d_in[7];
    const float* Whh     = (const float*)d_in[8];
    const float* b_ih    = (const float*)d_in[9];
    const float* b_hh    = (const float*)d_in[10];
    const float* Wfc     = (const float*)d_in[11];
    const float* bfc     = (const float*)d_in[12];

    float* pred = (float*)d_out;
    float* h1o  = pred + (size_t)BB * VV;
    float* c1o  = h1o + (size_t)BB * HH;

    const int smem_attn = (CROWS * TWOH + TWOH) * sizeof(float);   // 72 KB
    const int smem_gemm = 2 * STAGE;                               // 61440
    cudaFuncSetAttribute(k_attn, cudaFuncAttributeMaxDynamicSharedMemorySize, smem_attn);
    cudaFuncSetAttribute(k_gates_mm, cudaFuncAttributeMaxDynamicSharedMemorySize, smem_gemm);
    cudaFuncSetAttribute(k_fc_mm, cudaFuncAttributeMaxDynamicSharedMemorySize, smem_gemm);

    k_hw<<<BB, 128>>>(hidden, Wen);
    k_attn<<<dim3(NCHUNK, BB), 256, smem_attn>>>(enc, Wen, be);
    k_combine<<<BB, 256>>>(emb, x, hidden);
    k_gates_mm<<<dim3(G4 / MT, NSPLIT), 256, smem_gemm>>>(Wih, Whh);
    k_lstm<<<(BB * HH) / 256, 256>>>(b_ih, b_hh, cell, h1o, c1o);
    k_fc_mm<<<VV / MT, 256, smem_gemm>>>(Wfc, bfc, pred);
}

// round 11
// speedup vs baseline: 1.4628x; 1.1668x over previous
#include <cuda_runtime.h>
#include <cstdint>

#define SS 512
#define BB 64
#define HH 1024
#define EE 512
#define VV 32000
#define TWOH 2048
#define KTOT 3584
#define G4 4096
#define NCHUNK 64
#define CROWS 8
#define NSPLIT 14
#define KSPLIT 256
#define FCSPLIT 2
#define FCK 512             // K per fc split

// HMMA GEMM tile config (R5/R10-proven structure)
#define MT 128              // m rows per CTA (weight rows)
#define KC 32               // k per chunk
#define OFF_AHI 0
#define OFF_ALO 10240       // 128*80
#define OFF_BHI 20480
#define OFF_BLO 25600
#define STAGE 30720

// ---------------- scratch ----------------------------------------------------
__device__ float g_hw[BB];
__device__ float g_eM[BB * NCHUNK];
__device__ float g_eL[BB * NCHUNK];
__device__ float g_ctx[(size_t)BB * NCHUNK * TWOH];
__device__ unsigned short g_Bhi[BB * KTOT];   // rnn_in bf16 hi  [b][k]
__device__ unsigned short g_Blo[BB * KTOT];
__device__ unsigned short g_h1hi[BB * HH];
__device__ unsigned short g_h1lo[BB * HH];
__device__ float g_gatesP[NSPLIT * G4 * BB];  // [s][m][b]
__device__ float g_fcP[(size_t)FCSPLIT * BB * VV];  // [s][b][v]

__device__ __forceinline__ float sigm(float x) { return 1.f / (1.f + __expf(-x)); }

__device__ __forceinline__ void cpa16(uint32_t s, const void* g) {
    asm volatile("cp.async.cg.shared.global [%0], [%1], 16;" :: "r"(s), "l"(g));
}
__device__ __forceinline__ void cpa_commit() { asm volatile("cp.async.commit_group;"); }
__device__ __forceinline__ void cpa_wait0()  { asm volatile("cp.async.wait_group 0;"); }

__device__ __forceinline__ void ldsm4(uint32_t* r, uint32_t addr) {
    asm volatile("ldmatrix.sync.aligned.m8n8.x4.shared.b16 {%0,%1,%2,%3}, [%4];"
        : "=r"(r[0]), "=r"(r[1]), "=r"(r[2]), "=r"(r[3]) : "r"(addr));
}
__device__ __forceinline__ void mma16816(float* d, const uint32_t* a, const uint32_t* b) {
    asm volatile("mma.sync.aligned.m16n8k16.row.col.f32.bf16.bf16.f32 "
        "{%0,%1,%2,%3},{%4,%5,%6,%7},{%8,%9},{%0,%1,%2,%3};"
        : "+f"(d[0]), "+f"(d[1]), "+f"(d[2]), "+f"(d[3])
        : "r"(a[0]), "r"(a[1]), "r"(a[2]), "r"(a[3]), "r"(b[0]), "r"(b[1]));
}
__device__ __forceinline__ void st4(uint32_t a, uint32_t x, uint32_t y, uint32_t z, uint32_t w) {
    asm volatile("st.shared.v4.u32 [%0], {%1,%2,%3,%4};" :: "r"(a), "r"(x), "r"(y), "r"(z), "r"(w));
}

__device__ __forceinline__ void split16(float x, unsigned short& hi, unsigned short& lo) {
    uint32_t bx = __float_as_uint(x);
    hi = (unsigned short)(bx >> 16);
    float lf = x - __uint_as_float(bx & 0xFFFF0000u);
    lo = (unsigned short)(__float_as_uint(lf) >> 16);
}

// ---------------- K0 ----------------------------------------------------------
__global__ void k_hw(const float* __restrict__ hidden, const float* __restrict__ Wen) {
    int b = blockIdx.x, tid = threadIdx.x;
    float p = 0.f;
    for (int k = tid; k < HH; k += 128) p += hidden[b * HH + k] * Wen[k];
    __shared__ float red[128];
    red[tid] = p; __syncthreads();
    for (int o = 64; o >= 32; o >>= 1) { if (tid < o) red[tid] += red[tid + o]; __syncthreads(); }
    if (tid < 32) {
        float v = red[tid];
        for (int o = 16; o; o >>= 1) v += __shfl_xor_sync(~0u, v, o);
        if (tid == 0) g_hw[b] = v;
    }
}

// ---------------- K1: attention --------------------------------------------
__global__ __launch_bounds__(256)
void k_attn(const float* __restrict__ enc, const float* __restrict__ Wen,
            const float* __restrict__ be) {
    extern __shared__ float sm[];
    float* rows = sm;
    float* we   = sm + CROWS * TWOH;
    __shared__ float sE[CROWS];
    const int chunk = blockIdx.x, b = blockIdx.y, tid = threadIdx.x;
    const int s0 = chunk * CROWS;
    uint32_t s_rows = (uint32_t)__cvta_generic_to_shared(rows);
    uint32_t s_we   = (uint32_t)__cvta_generic_to_shared(we);

    for (int i = tid; i < TWOH / 4; i += 256)
        cpa16(s_we + i * 16, (const float4*)(Wen + HH) + i);
    for (int i = tid; i < CROWS * (TWOH / 4); i += 256) {
        int r = i >> 9, c = i & 511;
        cpa16(s_rows + (r * (TWOH / 4) + c) * 16,
              (const float4*)(enc + ((size_t)(s0 + r) * BB + b) * TWOH) + c);
    }
    cpa_commit(); cpa_wait0();
    __syncthreads();

    const int w = tid >> 5, lane = tid & 31;
    const float hwb = g_hw[b], bev = be[0];
    {
        float p = 0.f;
        const float* row = rows + w * TWOH;
        for (int j = lane; j < TWOH; j += 32) p += row[j] * we[j];
        for (int o = 16; o; o >>= 1) p += __shfl_xor_sync(~0u, p, o);
        if (lane == 0) sE[w] = fmaxf(p + hwb + bev, 0.f);
    }
    __syncthreads();
    float m = -1e30f;
#pragma unroll
    for (int i = 0; i < CROWS; i++) m = fmaxf(m, sE[i]);
    float pe[CROWS]; float l = 0.f;
#pragma unroll
    for (int i = 0; i < CROWS; i++) { pe[i] = __expf(sE[i] - m); l += pe[i]; }
    float* dst = g_ctx + ((size_t)b * NCHUNK + chunk) * TWOH;
    for (int d = tid; d < TWOH; d += 256) {
        float v = 0.f;
#pragma unroll
        for (int i = 0; i < CROWS; i++) v += pe[i] * rows[i * TWOH + d];
        dst[d] = v;
    }
    if (tid == 0) { g_eM[b * NCHUNK + chunk] = m; g_eL[b * NCHUNK + chunk] = l; }
}

// ---------------- K2: combine (8-way parallel over features) ----------------
__global__ void k_combine(const float* __restrict__ emb_table,
                          const int* __restrict__ x,
                          const float* __restrict__ hidden) {
    int b = blockIdx.x, y = blockIdx.y, tid = threadIdx.x;
    __shared__ float ssc[NCHUNK];
    __shared__ float sInv;
    if (tid == 0) {
        float M = -1e30f;
        for (int i = 0; i < NCHUNK; i++) M = fmaxf(M, g_eM[b * NCHUNK + i]);
        float L = 0.f;
        for (int i = 0; i < NCHUNK; i++) {
            float s = __expf(g_eM[b * NCHUNK + i] - M);
            ssc[i] = s;
            L += s * g_eL[b * NCHUNK + i];
        }
        sInv = 1.f / L;
    }
    __syncthreads();
    float inv = sInv;
    unsigned short hi, lo;
    // ctx slice: 256 features per block
    {
        int d = y * 256 + tid;
        float v = 0.f;
#pragma unroll 8
        for (int i = 0; i < NCHUNK; i++)
            v += ssc[i] * g_ctx[((size_t)b * NCHUNK + i) * TWOH + d];
        split16(v * inv, hi, lo);
        g_Bhi[b * KTOT + d] = hi; g_Blo[b * KTOT + d] = lo;
    }
    int xb = x[b];
    // emb slice: 64 per block
    if (tid < 64) {
        int j = y * 64 + tid;
        split16(emb_table[(size_t)xb * EE + j], hi, lo);
        g_Bhi[b * KTOT + TWOH + j] = hi; g_Blo[b * KTOT + TWOH + j] = lo;
    }
    // h0 slice: 128 per block
    if (tid < 128) {
        int j = y * 128 + tid;
        split16(hidden[b * HH + j], hi, lo);
        g_Bhi[b * KTOT + TWOH + EE + j] = hi; g_Blo[b * KTOT + TWOH + EE + j] = lo;
    }
}

// ================= HMMA GEMM pieces (R10 structure) ============================
__device__ __forceinline__ void stsA_conv(uint32_t sb, const float4* pa, int cm, int ckq) {
    uint32_t h[8], lw[8];
#pragma unroll
    for (int i = 0; i < 4; i++) {
        uint32_t bx = __float_as_uint(pa[i].x), by = __float_as_uint(pa[i].y);
        uint32_t bz = __float_as_uint(pa[i].z), bw = __float_as_uint(pa[i].w);
        h[2 * i]     = __byte_perm(bx, by, 0x7632);
        h[2 * i + 1] = __byte_perm(bz, bw, 0x7632);
        float lx = pa[i].x - __uint_as_float(bx & 0xFFFF0000u);
        float ly = pa[i].y - __uint_as_float(by & 0xFFFF0000u);
        float lz = pa[i].z - __uint_as_float(bz & 0xFFFF0000u);
        float lv = pa[i].w - __uint_as_float(bw & 0xFFFF0000u);
        lw[2 * i]     = __byte_perm(__float_as_uint(lx), __float_as_uint(ly), 0x7632);
        lw[2 * i + 1] = __byte_perm(__float_as_uint(lz), __float_as_uint(lv), 0x7632);
    }
    uint32_t d = sb + OFF_AHI + cm * 80 + ckq * 2;
    st4(d, h[0], h[1], h[2], h[3]);
    st4(d + 16, h[4], h[5], h[6], h[7]);
    d = sb + OFF_ALO + cm * 80 + ckq * 2;
    st4(d, lw[0], lw[1], lw[2], lw[3]);
    st4(d + 16, lw[4], lw[5], lw[6], lw[7]);
}

__device__ __forceinline__ void domma(uint32_t sb, float (*acc)[4], int w, int l) {
    const int arow = w * 16 + (l & 7) + ((l >> 3) & 1) * 8;
    const int acol = ((l >> 4) & 1) * 8;
    const int brof = ((l >> 4) & 1) * 8 + (l & 7);
    const int bcol = ((l >> 3) & 1) * 8;
#pragma unroll
    for (int ks = 0; ks < 2; ks++) {
        uint32_t ahi[4], alo[4];
        uint32_t ao = arow * 80 + (ks * 16 + acol) * 2;
        ldsm4(ahi, sb + OFF_AHI + ao);
        ldsm4(alo, sb + OFF_ALO + ao);
#pragma unroll
        for (int p = 0; p < 4; p++) {
            uint32_t bh[4], bl[4];
            uint32_t bo = (p * 16 + brof) * 80 + (ks * 16 + bcol) * 2;
            ldsm4(bh, sb + OFF_BHI + bo);
            ldsm4(bl, sb + OFF_BLO + bo);
            mma16816(acc[2 * p],     ahi, bh);
            mma16816(acc[2 * p + 1], ahi, bh + 2);
            mma16816(acc[2 * p],     alo, bh);
            mma16816(acc[2 * p + 1], alo, bh + 2);
            mma16816(acc[2 * p],     ahi, bl);
            mma16816(acc[2 * p + 1], ahi, bl + 2);
        }
    }
}

// ---------------- K3: gates GEMM  grid(32, 14) --------------------------------
__global__ __launch_bounds__(256, 3)
void k_gates_mm(const float* __restrict__ Wih, const float* __restrict__ Whh) {
    extern __shared__ char dsm[];
    uint32_t base = (uint32_t)__cvta_generic_to_shared(dsm);
    const int tid = threadIdx.x, w = tid >> 5, l = tid & 31;
    const int mbase = blockIdx.x * MT;
    const int split = blockIdx.y;
    const int kstart = split * KSPLIT;
    const int NCH = KSPLIT / KC;     // 8

    const int cm = tid >> 1, ckq = (tid & 1) * 16;
    const int bn = tid >> 2, bq = (tid & 3) * 16;

    float acc[8][4];
#pragma unroll
    for (int i = 0; i < 8; i++)
#pragma unroll
        for (int j = 0; j < 4; j++) acc[i][j] = 0.f;

    float4 pa[4];
    auto ldgA = [&](int kg) {
        const float* src = (kg < 2560)
            ? Wih + (size_t)(mbase + cm) * 2560 + kg
            : Whh + (size_t)(mbase + cm) * 1024 + (kg - 2560);
#pragma unroll
        for (int i = 0; i < 4; i++) pa[i] = *(const float4*)(src + ckq + i * 4);
    };
    auto cpaB = [&](int kg, uint32_t sb) {
        cpa16(sb + OFF_BHI + bn * 80 + bq, (const char*)g_Bhi + (size_t)bn * KTOT * 2 + kg * 2 + bq);
        cpa16(sb + OFF_BLO + bn * 80 + bq, (const char*)g_Blo + (size_t)bn * KTOT * 2 + kg * 2 + bq);
        cpa_commit();
    };

    ldgA(kstart);
    cpaB(kstart, base);
    for (int c = 0; c < NCH; c++) {
        uint32_t sb = base + (c & 1) * STAGE;
        stsA_conv(sb, pa, cm, ckq);
        cpa_wait0();
        __syncthreads();
        if (c + 1 < NCH) {
            int kg = kstart + (c + 1) * KC;
            ldgA(kg);
            cpaB(kg, base + ((c + 1) & 1) * STAGE);
        }
        domma(sb, acc, w, l);
        __syncthreads();
    }

    const int gid = l >> 2, tig = (l & 3) * 2;
    float* outp = g_gatesP + ((size_t)split * G4 + mbase + w * 16) * BB;
#pragma unroll
    for (int no = 0; no < 8; no++) {
        *(float2*)(outp + gid * BB + no * 8 + tig)       = make_float2(acc[no][0], acc[no][1]);
        *(float2*)(outp + (gid + 8) * BB + no * 8 + tig) = make_float2(acc[no][2], acc[no][3]);
    }
}

// ---------------- K3b: LSTM ---------------------------------------------------
__global__ void k_lstm(const float* __restrict__ b_ih, const float* __restrict__ b_hh,
                       const float* __restrict__ cell,
                       float* __restrict__ h1o, float* __restrict__ c1o) {
    int idx = blockIdx.x * blockDim.x + threadIdx.x;
    int b = idx & 63, j = idx >> 6;
    float gi = 0, gf = 0, gg = 0, go = 0;
#pragma unroll
    for (int s = 0; s < NSPLIT; s++) {
        const float* gp = g_gatesP + (size_t)s * G4 * BB;
        gi += gp[(j) * BB + b];
        gf += gp[(1024 + j) * BB + b];
        gg += gp[(2048 + j) * BB + b];
        go += gp[(3072 + j) * BB + b];
    }
    gi += b_ih[j]        + b_hh[j];
    gf += b_ih[1024 + j] + b_hh[1024 + j];
    gg += b_ih[2048 + j] + b_hh[2048 + j];
    go += b_ih[3072 + j] + b_hh[3072 + j];
    float c0 = cell[b * HH + j];
    float c1 = sigm(gf) * c0 + sigm(gi) * tanhf(gg);
    float h1 = sigm(go) * tanhf(c1);
    h1o[b * HH + j] = h1;
    c1o[b * HH + j] = c1;
    unsigned short hi, lo;
    split16(h1, hi, lo);
    g_h1hi[b * HH + j] = hi;
    g_h1lo[b * HH + j] = lo;
}

// ---------------- K4: FC GEMM  grid(250, 2) k-split ----------------------------
__global__ __launch_bounds__(256, 3)
void k_fc_mm(const float* __restrict__ Wfc) {
    extern __shared__ char dsm[];
    uint32_t base = (uint32_t)__cvta_generic_to_shared(dsm);
    const int tid = threadIdx.x, w = tid >> 5, l = tid & 31;
    const int mbase = blockIdx.x * MT;
    const int split = blockIdx.y;
    const int kstart = split * FCK;
    const int NCH = FCK / KC;        // 16

    const int cm = tid >> 1, ckq = (tid & 1) * 16;
    const int bn = tid >> 2, bq = (tid & 3) * 16;

    float acc[8][4];
#pragma unroll
    for (int i = 0; i < 8; i++)
#pragma unroll
        for (int j = 0; j < 4; j++) acc[i][j] = 0.f;

    float4 pa[4];
    auto ldgA = [&](int kg) {
        const float* src = Wfc + (size_t)(mbase + cm) * HH + kg;
#pragma unroll
        for (int i = 0; i < 4; i++) pa[i] = *(const float4*)(src + ckq + i * 4);
    };
    auto cpaB = [&](int kg, uint32_t sb) {
        cpa16(sb + OFF_BHI + bn * 80 + bq, (const char*)g_h1hi + (size_t)bn * HH * 2 + kg * 2 + bq);
        cpa16(sb + OFF_BLO + bn * 80 + bq, (const char*)g_h1lo + (size_t)bn * HH * 2 + kg * 2 + bq);
        cpa_commit();
    };

    ldgA(kstart);
    cpaB(kstart, base);
    for (int c = 0; c < NCH; c++) {
        uint32_t sb = base + (c & 1) * STAGE;
        stsA_conv(sb, pa, cm, ckq);
        cpa_wait0();
        __syncthreads();
        if (c + 1 < NCH) {
            int kg = kstart + (c + 1) * KC;
            ldgA(kg);
            cpaB(kg, base + ((c + 1) & 1) * STAGE);
        }
        domma(sb, acc, w, l);
        __syncthreads();
    }
    __syncthreads();

    // epilogue: transpose through smem, coalesced store to partial buffer [s][b][v]
    float* ts = (float*)dsm;      // [64][132]
    const int gid = l >> 2, tig = (l & 3) * 2;
#pragma unroll
    for (int no = 0; no < 8; no++) {
        int n = no * 8 + tig;
        ts[n * 132 + w * 16 + gid]           = acc[no][0];
        ts[(n + 1) * 132 + w * 16 + gid]     = acc[no][1];
        ts[n * 132 + w * 16 + gid + 8]       = acc[no][2];
        ts[(n + 1) * 132 + w * 16 + gid + 8] = acc[no][3];
    }
    __syncthreads();
    {
        int b = tid >> 2, q = tid & 3;
        const float* srow = ts + b * 132 + q * 32;
        float* drow = g_fcP + (size_t)split * BB * VV + (size_t)b * VV + mbase + q * 32;
#pragma unroll
        for (int i = 0; i < 8; i++)
            *(float4*)(drow + i * 4) = make_float4(srow[i * 4], srow[i * 4 + 1],
                                                   srow[i * 4 + 2], srow[i * 4 + 3]);
    }
}

// ---------------- K4b: fc reduce + bias ----------------------------------------
__global__ void k_fcred(const float* __restrict__ bfc, float* __restrict__ pred) {
    size_t i4 = (size_t)blockIdx.x * blockDim.x + threadIdx.x;   // float4 index
    size_t i = i4 * 4;                                           // element index
    int v = (int)(i % VV);
    float4 p0 = *(const float4*)(g_fcP + i);
    float4 p1 = *(const float4*)(g_fcP + (size_t)BB * VV + i);
    float4 bb = *(const float4*)(bfc + v);
    *(float4*)(pred + i) = make_float4(p0.x + p1.x + bb.x, p0.y + p1.y + bb.y,
                                       p0.z + p1.z + bb.z, p0.w + p1.w + bb.w);
}

// ---------------- launch --------------------------------------------------------
extern "C" void kernel_launch(void* const* d_in, const int* in_sizes, int n_in,
                              void* d_out, int out_size) {
    const int*   x       = (const int*)  d_in[0];
    const float* enc     = (const float*)d_in[1];
    const float* hidden  = (const float*)d_in[2];
    const float* cell    = (const float*)d_in[3];
    const float* emb     = (const float*)d_in[4];
    const float* Wen     = (const float*)d_in[5];
    const float* be      = (const float*)d_in[6];
    const float* Wih     = (const float*)d_in[7];
    const float* Whh     = (const float*)d_in[8];
    const float* b_ih    = (const float*)d_in[9];
    const float* b_hh    = (const float*)d_in[10];
    const float* Wfc     = (const float*)d_in[11];
    const float* bfc     = (const float*)d_in[12];

    float* pred = (float*)d_out;
    float* h1o  = pred + (size_t)BB * VV;
    float* c1o  = h1o + (size_t)BB * HH;

    const int smem_attn = (CROWS * TWOH + TWOH) * sizeof(float);   // 72 KB
    const int smem_gemm = 2 * STAGE;                               // 61440
    cudaFuncSetAttribute(k_attn, cudaFuncAttributeMaxDynamicSharedMemorySize, smem_attn);
    cudaFuncSetAttribute(k_gates_mm, cudaFuncAttributeMaxDynamicSharedMemorySize, smem_gemm);
    cudaFuncSetAttribute(k_fc_mm, cudaFuncAttributeMaxDynamicSharedMemorySize, smem_gemm);

    k_hw<<<BB, 128>>>(hidden, Wen);
    k_attn<<<dim3(NCHUNK, BB), 256, smem_attn>>>(enc, Wen, be);
    k_combine<<<dim3(BB, 8), 256>>>(emb, x, hidden);
    k_gates_mm<<<dim3(G4 / MT, NSPLIT), 256, smem_gemm>>>(Wih, Whh);
    k_lstm<<<(BB * HH) / 256, 256>>>(b_ih, b_hh, cell, h1o, c1o);
    k_fc_mm<<<dim3(VV / MT, FCSPLIT), 256, smem_gemm>>>(Wfc);
    k_fcred<<<(BB * VV / 4) / 256, 256>>>(bfc, pred);
}

// round 12
// speedup vs baseline: 1.5645x; 1.0695x over previous
#include <cuda_runtime.h>
#include <cstdint>

#define SS 512
#define BB 64
#define HH 1024
#define EE 512
#define VV 32000
#define TWOH 2048
#define KTOT 3584
#define G4 4096
#define NCHUNK 64
#define CROWS 8
#define NSPLIT 8
#define KSPLIT 448

// HMMA GEMM tile config: MT=64, 4 CTA/SM
#define MT 64
#define KC 32
#define OFF_AHI 0
#define OFF_ALO 5120        // 64*80
#define OFF_BHI 10240
#define OFF_BLO 15360
#define STAGE 20480

// ---------------- scratch ----------------------------------------------------
__device__ float g_hw[BB];
__device__ float g_eM[BB * NCHUNK];
__device__ float g_eL[BB * NCHUNK];
__device__ float g_ctx[(size_t)BB * NCHUNK * TWOH];
__device__ unsigned short g_Bhi[BB * KTOT];
__device__ unsigned short g_Blo[BB * KTOT];
__device__ unsigned short g_h1hi[BB * HH];
__device__ unsigned short g_h1lo[BB * HH];
__device__ float g_gatesP[NSPLIT * G4 * BB];  // [s][m][b]

__device__ __forceinline__ float sigm(float x) { return 1.f / (1.f + __expf(-x)); }

__device__ __forceinline__ void cpa16(uint32_t s, const void* g) {
    asm volatile("cp.async.cg.shared.global [%0], [%1], 16;" :: "r"(s), "l"(g));
}
__device__ __forceinline__ void cpa_commit() { asm volatile("cp.async.commit_group;"); }
__device__ __forceinline__ void cpa_wait0()  { asm volatile("cp.async.wait_group 0;"); }

__device__ __forceinline__ void ldsm4(uint32_t* r, uint32_t addr) {
    asm volatile("ldmatrix.sync.aligned.m8n8.x4.shared.b16 {%0,%1,%2,%3}, [%4];"
        : "=r"(r[0]), "=r"(r[1]), "=r"(r[2]), "=r"(r[3]) : "r"(addr));
}
__device__ __forceinline__ void mma16816(float* d, const uint32_t* a, const uint32_t* b) {
    asm volatile("mma.sync.aligned.m16n8k16.row.col.f32.bf16.bf16.f32 "
        "{%0,%1,%2,%3},{%4,%5,%6,%7},{%8,%9},{%0,%1,%2,%3};"
        : "+f"(d[0]), "+f"(d[1]), "+f"(d[2]), "+f"(d[3])
        : "r"(a[0]), "r"(a[1]), "r"(a[2]), "r"(a[3]), "r"(b[0]), "r"(b[1]));
}
__device__ __forceinline__ void st4(uint32_t a, uint32_t x, uint32_t y, uint32_t z, uint32_t w) {
    asm volatile("st.shared.v4.u32 [%0], {%1,%2,%3,%4};" :: "r"(a), "r"(x), "r"(y), "r"(z), "r"(w));
}

__device__ __forceinline__ void split16(float x, unsigned short& hi, unsigned short& lo) {
    uint32_t bx = __float_as_uint(x);
    hi = (unsigned short)(bx >> 16);
    float lf = x - __uint_as_float(bx & 0xFFFF0000u);
    lo = (unsigned short)(__float_as_uint(lf) >> 16);
}

// ---------------- K0 ----------------------------------------------------------
__global__ void k_hw(const float* __restrict__ hidden, const float* __restrict__ Wen) {
    int b = blockIdx.x, tid = threadIdx.x;
    float p = 0.f;
    for (int k = tid; k < HH; k += 128) p += hidden[b * HH + k] * Wen[k];
    __shared__ float red[128];
    red[tid] = p; __syncthreads();
    for (int o = 64; o >= 32; o >>= 1) { if (tid < o) red[tid] += red[tid + o]; __syncthreads(); }
    if (tid < 32) {
        float v = red[tid];
        for (int o = 16; o; o >>= 1) v += __shfl_xor_sync(~0u, v, o);
        if (tid == 0) g_hw[b] = v;
    }
}

// ---------------- K1: attention --------------------------------------------
__global__ __launch_bounds__(256)
void k_attn(const float* __restrict__ enc, const float* __restrict__ Wen,
            const float* __restrict__ be) {
    extern __shared__ float sm[];
    float* rows = sm;
    float* we   = sm + CROWS * TWOH;
    __shared__ float sE[CROWS];
    const int chunk = blockIdx.x, b = blockIdx.y, tid = threadIdx.x;
    const int s0 = chunk * CROWS;
    uint32_t s_rows = (uint32_t)__cvta_generic_to_shared(rows);
    uint32_t s_we   = (uint32_t)__cvta_generic_to_shared(we);

    for (int i = tid; i < TWOH / 4; i += 256)
        cpa16(s_we + i * 16, (const float4*)(Wen + HH) + i);
    for (int i = tid; i < CROWS * (TWOH / 4); i += 256) {
        int r = i >> 9, c = i & 511;
        cpa16(s_rows + (r * (TWOH / 4) + c) * 16,
              (const float4*)(enc + ((size_t)(s0 + r) * BB + b) * TWOH) + c);
    }
    cpa_commit(); cpa_wait0();
    __syncthreads();

    const int w = tid >> 5, lane = tid & 31;
    const float hwb = g_hw[b], bev = be[0];
    {
        float p = 0.f;
        const float* row = rows + w * TWOH;
        for (int j = lane; j < TWOH; j += 32) p += row[j] * we[j];
        for (int o = 16; o; o >>= 1) p += __shfl_xor_sync(~0u, p, o);
        if (lane == 0) sE[w] = fmaxf(p + hwb + bev, 0.f);
    }
    __syncthreads();
    float m = -1e30f;
#pragma unroll
    for (int i = 0; i < CROWS; i++) m = fmaxf(m, sE[i]);
    float pe[CROWS]; float l = 0.f;
#pragma unroll
    for (int i = 0; i < CROWS; i++) { pe[i] = __expf(sE[i] - m); l += pe[i]; }
    float* dst = g_ctx + ((size_t)b * NCHUNK + chunk) * TWOH;
    for (int d = tid; d < TWOH; d += 256) {
        float v = 0.f;
#pragma unroll
        for (int i = 0; i < CROWS; i++) v += pe[i] * rows[i * TWOH + d];
        dst[d] = v;
    }
    if (tid == 0) { g_eM[b * NCHUNK + chunk] = m; g_eL[b * NCHUNK + chunk] = l; }
}

// ---------------- K2: combine (8-way parallel over features) ----------------
__global__ void k_combine(const float* __restrict__ emb_table,
                          const int* __restrict__ x,
                          const float* __restrict__ hidden) {
    int b = blockIdx.x, y = blockIdx.y, tid = threadIdx.x;
    __shared__ float ssc[NCHUNK];
    __shared__ float sInv;
    if (tid == 0) {
        float M = -1e30f;
        for (int i = 0; i < NCHUNK; i++) M = fmaxf(M, g_eM[b * NCHUNK + i]);
        float L = 0.f;
        for (int i = 0; i < NCHUNK; i++) {
            float s = __expf(g_eM[b * NCHUNK + i] - M);
            ssc[i] = s;
            L += s * g_eL[b * NCHUNK + i];
        }
        sInv = 1.f / L;
    }
    __syncthreads();
    float inv = sInv;
    unsigned short hi, lo;
    {
        int d = y * 256 + tid;
        float v = 0.f;
#pragma unroll 8
        for (int i = 0; i < NCHUNK; i++)
            v += ssc[i] * g_ctx[((size_t)b * NCHUNK + i) * TWOH + d];
        split16(v * inv, hi, lo);
        g_Bhi[b * KTOT + d] = hi; g_Blo[b * KTOT + d] = lo;
    }
    int xb = x[b];
    if (tid < 64) {
        int j = y * 64 + tid;
        split16(emb_table[(size_t)xb * EE + j], hi, lo);
        g_Bhi[b * KTOT + TWOH + j] = hi; g_Blo[b * KTOT + TWOH + j] = lo;
    }
    if (tid < 128) {
        int j = y * 128 + tid;
        split16(hidden[b * HH + j], hi, lo);
        g_Bhi[b * KTOT + TWOH + EE + j] = hi; g_Blo[b * KTOT + TWOH + EE + j] = lo;
    }
}

// ================= HMMA GEMM pieces (MT=64) ====================================
// A copy: 64 rows x 32k fp32 -> bf16 hi/lo. thread: row=tid>>2, qq=(tid&3)*8 floats
__device__ __forceinline__ void stsA_conv(uint32_t sb, const float4* pa, int row, int qq) {
    uint32_t h[4], lw[4];
#pragma unroll
    for (int i = 0; i < 2; i++) {
        uint32_t bx = __float_as_uint(pa[i].x), by = __float_as_uint(pa[i].y);
        uint32_t bz = __float_as_uint(pa[i].z), bw = __float_as_uint(pa[i].w);
        h[2 * i]     = __byte_perm(bx, by, 0x7632);
        h[2 * i + 1] = __byte_perm(bz, bw, 0x7632);
        float lx = pa[i].x - __uint_as_float(bx & 0xFFFF0000u);
        float ly = pa[i].y - __uint_as_float(by & 0xFFFF0000u);
        float lz = pa[i].z - __uint_as_float(bz & 0xFFFF0000u);
        float lv = pa[i].w - __uint_as_float(bw & 0xFFFF0000u);
        lw[2 * i]     = __byte_perm(__float_as_uint(lx), __float_as_uint(ly), 0x7632);
        lw[2 * i + 1] = __byte_perm(__float_as_uint(lz), __float_as_uint(lv), 0x7632);
    }
    uint32_t d = sb + OFF_AHI + row * 80 + qq * 2;
    st4(d, h[0], h[1], h[2], h[3]);
    d = sb + OFF_ALO + row * 80 + qq * 2;
    st4(d, lw[0], lw[1], lw[2], lw[3]);
}

// warp MMA: warp covers 16m x 32n. wq=w&3 (m quarter), wh=w>>2 (n half)
__device__ __forceinline__ void domma(uint32_t sb, float (*acc)[4], int w, int l) {
    const int wq = w & 3, wh = w >> 2;
    const int arow = wq * 16 + (l & 7) + ((l >> 3) & 1) * 8;
    const int acol = ((l >> 4) & 1) * 8;
    const int brof = wh * 32 + ((l >> 4) & 1) * 8 + (l & 7);
    const int bcol = ((l >> 3) & 1) * 8;
#pragma unroll
    for (int ks = 0; ks < 2; ks++) {
        uint32_t ahi[4], alo[4];
        uint32_t ao = arow * 80 + (ks * 16 + acol) * 2;
        ldsm4(ahi, sb + OFF_AHI + ao);
        ldsm4(alo, sb + OFF_ALO + ao);
#pragma unroll
        for (int p = 0; p < 2; p++) {
            uint32_t bh[4], bl[4];
            uint32_t bo = (p * 16 + brof) * 80 + (ks * 16 + bcol) * 2;
            ldsm4(bh, sb + OFF_BHI + bo);
            ldsm4(bl, sb + OFF_BLO + bo);
            mma16816(acc[2 * p],     ahi, bh);
            mma16816(acc[2 * p + 1], ahi, bh + 2);
            mma16816(acc[2 * p],     alo, bh);
            mma16816(acc[2 * p + 1], alo, bh + 2);
            mma16816(acc[2 * p],     ahi, bl);
            mma16816(acc[2 * p + 1], ahi, bl + 2);
        }
    }
}

// ---------------- K3: gates GEMM  grid(64, 8) --------------------------------
__global__ __launch_bounds__(256, 4)
void k_gates_mm(const float* __restrict__ Wih, const float* __restrict__ Whh) {
    extern __shared__ char dsm[];
    uint32_t base = (uint32_t)__cvta_generic_to_shared(dsm);
    const int tid = threadIdx.x, w = tid >> 5, l = tid & 31;
    const int mbase = blockIdx.x * MT;
    const int split = blockIdx.y;
    const int kstart = split * KSPLIT;
    const int NCH = KSPLIT / KC;     // 14

    const int arow = tid >> 2, aqq = (tid & 3) * 8;
    const int bn = tid >> 2, bq = (tid & 3) * 16;

    float acc[4][4];
#pragma unroll
    for (int i = 0; i < 4; i++)
#pragma unroll
        for (int j = 0; j < 4; j++) acc[i][j] = 0.f;

    float4 pa[2];
    auto ldgA = [&](int kg) {
        const float* src = (kg < 2560)
            ? Wih + (size_t)(mbase + arow) * 2560 + kg
            : Whh + (size_t)(mbase + arow) * 1024 + (kg - 2560);
        pa[0] = *(const float4*)(src + aqq);
        pa[1] = *(const float4*)(src + aqq + 4);
    };
    auto cpaB = [&](int kg, uint32_t sb) {
        cpa16(sb + OFF_BHI + bn * 80 + bq, (const char*)g_Bhi + (size_t)bn * KTOT * 2 + kg * 2 + bq);
        cpa16(sb + OFF_BLO + bn * 80 + bq, (const char*)g_Blo + (size_t)bn * KTOT * 2 + kg * 2 + bq);
        cpa_commit();
    };

    ldgA(kstart);
    cpaB(kstart, base);
    for (int c = 0; c < NCH; c++) {
        uint32_t sb = base + (c & 1) * STAGE;
        stsA_conv(sb, pa, arow, aqq);
        cpa_wait0();
        __syncthreads();
        if (c + 1 < NCH) {
            int kg = kstart + (c + 1) * KC;
            ldgA(kg);
            cpaB(kg, base + ((c + 1) & 1) * STAGE);
        }
        domma(sb, acc, w, l);
        __syncthreads();
    }

    const int wq = w & 3, wh = w >> 2;
    const int gid = l >> 2, tig = (l & 3) * 2;
    float* outp = g_gatesP + ((size_t)split * G4 + mbase + wq * 16) * BB;
#pragma unroll
    for (int j = 0; j < 4; j++) {
        int n = wh * 32 + j * 8 + tig;
        *(float2*)(outp + gid * BB + n)       = make_float2(acc[j][0], acc[j][1]);
        *(float2*)(outp + (gid + 8) * BB + n) = make_float2(acc[j][2], acc[j][3]);
    }
}

// ---------------- K3b: LSTM ---------------------------------------------------
__global__ void k_lstm(const float* __restrict__ b_ih, const float* __restrict__ b_hh,
                       const float* __restrict__ cell,
                       float* __restrict__ h1o, float* __restrict__ c1o) {
    int idx = blockIdx.x * blockDim.x + threadIdx.x;
    int b = idx & 63, j = idx >> 6;
    float gi = 0, gf = 0, gg = 0, go = 0;
#pragma unroll
    for (int s = 0; s < NSPLIT; s++) {
        const float* gp = g_gatesP + (size_t)s * G4 * BB;
        gi += gp[(j) * BB + b];
        gf += gp[(1024 + j) * BB + b];
        gg += gp[(2048 + j) * BB + b];
        go += gp[(3072 + j) * BB + b];
    }
    gi += b_ih[j]        + b_hh[j];
    gf += b_ih[1024 + j] + b_hh[1024 + j];
    gg += b_ih[2048 + j] + b_hh[2048 + j];
    go += b_ih[3072 + j] + b_hh[3072 + j];
    float c0 = cell[b * HH + j];
    float c1 = sigm(gf) * c0 + sigm(gi) * tanhf(gg);
    float h1 = sigm(go) * tanhf(c1);
    h1o[b * HH + j] = h1;
    c1o[b * HH + j] = c1;
    unsigned short hi, lo;
    split16(h1, hi, lo);
    g_h1hi[b * HH + j] = hi;
    g_h1lo[b * HH + j] = lo;
}

// ---------------- K4: FC GEMM  grid(500), K=1024, direct output ---------------
__global__ __launch_bounds__(256, 4)
void k_fc_mm(const float* __restrict__ Wfc, const float* __restrict__ bfc,
             float* __restrict__ pred) {
    extern __shared__ char dsm[];
    uint32_t base = (uint32_t)__cvta_generic_to_shared(dsm);
    const int tid = threadIdx.x, w = tid >> 5, l = tid & 31;
    const int mbase = blockIdx.x * MT;
    const int NCH = HH / KC;         // 32

    const int arow = tid >> 2, aqq = (tid & 3) * 8;
    const int bn = tid >> 2, bq = (tid & 3) * 16;

    float acc[4][4];
#pragma unroll
    for (int i = 0; i < 4; i++)
#pragma unroll
        for (int j = 0; j < 4; j++) acc[i][j] = 0.f;

    float4 pa[2];
    auto ldgA = [&](int kg) {
        const float* src = Wfc + (size_t)(mbase + arow) * HH + kg;
        pa[0] = *(const float4*)(src + aqq);
        pa[1] = *(const float4*)(src + aqq + 4);
    };
    auto cpaB = [&](int kg, uint32_t sb) {
        cpa16(sb + OFF_BHI + bn * 80 + bq, (const char*)g_h1hi + (size_t)bn * HH * 2 + kg * 2 + bq);
        cpa16(sb + OFF_BLO + bn * 80 + bq, (const char*)g_h1lo + (size_t)bn * HH * 2 + kg * 2 + bq);
        cpa_commit();
    };

    ldgA(0);
    cpaB(0, base);
    for (int c = 0; c < NCH; c++) {
        uint32_t sb = base + (c & 1) * STAGE;
        stsA_conv(sb, pa, arow, aqq);
        cpa_wait0();
        __syncthreads();
        if (c + 1 < NCH) {
            int kg = (c + 1) * KC;
            ldgA(kg);
            cpaB(kg, base + ((c + 1) & 1) * STAGE);
        }
        domma(sb, acc, w, l);
        __syncthreads();
    }
    __syncthreads();

    // epilogue: bias + transpose through smem [n=64][m=68], coalesced store
    float* ts = (float*)dsm;
    const int wq = w & 3, wh = w >> 2;
    const int gid = l >> 2, tig = (l & 3) * 2;
    float bias0 = bfc[mbase + wq * 16 + gid];
    float bias1 = bfc[mbase + wq * 16 + gid + 8];
#pragma unroll
    for (int j = 0; j < 4; j++) {
        int n = wh * 32 + j * 8 + tig;
        ts[n * 68 + wq * 16 + gid]           = acc[j][0] + bias0;
        ts[(n + 1) * 68 + wq * 16 + gid]     = acc[j][1] + bias0;
        ts[n * 68 + wq * 16 + gid + 8]       = acc[j][2] + bias1;
        ts[(n + 1) * 68 + wq * 16 + gid + 8] = acc[j][3] + bias1;
    }
    __syncthreads();
    {
        int b = tid >> 2, q = tid & 3;
        const float* srow = ts + b * 68 + q * 16;
        float* drow = pred + (size_t)b * VV + mbase + q * 16;
#pragma unroll
        for (int i = 0; i < 4; i++)
            *(float4*)(drow + i * 4) = make_float4(srow[i * 4], srow[i * 4 + 1],
                                                   srow[i * 4 + 2], srow[i * 4 + 3]);
    }
}

// ---------------- launch --------------------------------------------------------
extern "C" void kernel_launch(void* const* d_in, const int* in_sizes, int n_in,
                              void* d_out, int out_size) {
    const int*   x       = (const int*)  d_in[0];
    const float* enc     = (const float*)d_in[1];
    const float* hidden  = (const float*)d_in[2];
    const float* cell    = (const float*)d_in[3];
    const float* emb     = (const float*)d_in[4];
    const float* Wen     = (const float*)d_in[5];
    const float* be      = (const float*)d_in[6];
    const float* Wih     = (const float*)d_in[7];
    const float* Whh     = (const float*)d_in[8];
    const float* b_ih    = (const float*)d_in[9];
    const float* b_hh    = (const float*)d_in[10];
    const float* Wfc     = (const float*)d_in[11];
    const float* bfc     = (const float*)d_in[12];

    float* pred = (float*)d_out;
    float* h1o  = pred + (size_t)BB * VV;
    float* c1o  = h1o + (size_t)BB * HH;

    const int smem_attn = (CROWS * TWOH + TWOH) * sizeof(float);   // 72 KB
    const int smem_gemm = 2 * STAGE;                               // 40960
    cudaFuncSetAttribute(k_attn, cudaFuncAttributeMaxDynamicSharedMemorySize, smem_attn);
    cudaFuncSetAttribute(k_gates_mm, cudaFuncAttributeMaxDynamicSharedMemorySize, smem_gemm);
    cudaFuncSetAttribute(k_fc_mm, cudaFuncAttributeMaxDynamicSharedMemorySize, smem_gemm);

    k_hw<<<BB, 128>>>(hidden, Wen);
    k_attn<<<dim3(NCHUNK, BB), 256, smem_attn>>>(enc, Wen, be);
    k_combine<<<dim3(BB, 8), 256>>>(emb, x, hidden);
    k_gates_mm<<<dim3(G4 / MT, NSPLIT), 256, smem_gemm>>>(Wih, Whh);
    k_lstm<<<(BB * HH) / 256, 256>>>(b_ih, b_hh, cell, h1o, c1o);
    k_fc_mm<<<VV / MT, 256, smem_gemm>>>(Wfc, bfc, pred);
}

// round 13
// speedup vs baseline: 1.6448x; 1.0513x over previous
#include <cuda_runtime.h>
#include <cstdint>

#define SS 512
#define BB 64
#define HH 1024
#define EE 512
#define VV 32000
#define TWOH 2048
#define KTOT 3584
#define G4 4096
#define NCHUNK 32           // 32 chunks of 16 rows (2 stages of 8)
#define CROWS 8
#define NSPLIT 14
#define KSPLIT 256

// gates GEMM: MT=128 (R10-proven)
#define GMT 128
#define KC 32
#define G_AHI 0
#define G_ALO 10240
#define G_BHI 20480
#define G_BLO 25600
#define G_STAGE 30720
// fc GEMM: MT=64 (R12-proven)
#define FMT 64
#define F_AHI 0
#define F_ALO 5120
#define F_BHI 10240
#define F_BLO 15360
#define F_STAGE 20480

// ---------------- scratch ----------------------------------------------------
__device__ float g_hw[BB];
__device__ float g_eM[BB * NCHUNK];
__device__ float g_eL[BB * NCHUNK];
__device__ float g_ctx[(size_t)BB * NCHUNK * TWOH];
__device__ unsigned short g_Bhi[BB * KTOT];
__device__ unsigned short g_Blo[BB * KTOT];
__device__ unsigned short g_h1hi[BB * HH];
__device__ unsigned short g_h1lo[BB * HH];
__device__ float g_gatesP[NSPLIT * G4 * BB];  // [s][m][b]

__device__ __forceinline__ float sigm(float x) { return 1.f / (1.f + __expf(-x)); }

__device__ __forceinline__ void cpa16(uint32_t s, const void* g) {
    asm volatile("cp.async.cg.shared.global [%0], [%1], 16;" :: "r"(s), "l"(g));
}
__device__ __forceinline__ void cpa_commit() { asm volatile("cp.async.commit_group;"); }
__device__ __forceinline__ void cpa_wait0()  { asm volatile("cp.async.wait_group 0;"); }

__device__ __forceinline__ void ldsm4(uint32_t* r, uint32_t addr) {
    asm volatile("ldmatrix.sync.aligned.m8n8.x4.shared.b16 {%0,%1,%2,%3}, [%4];"
        : "=r"(r[0]), "=r"(r[1]), "=r"(r[2]), "=r"(r[3]) : "r"(addr));
}
__device__ __forceinline__ void mma16816(float* d, const uint32_t* a, const uint32_t* b) {
    asm volatile("mma.sync.aligned.m16n8k16.row.col.f32.bf16.bf16.f32 "
        "{%0,%1,%2,%3},{%4,%5,%6,%7},{%8,%9},{%0,%1,%2,%3};"
        : "+f"(d[0]), "+f"(d[1]), "+f"(d[2]), "+f"(d[3])
        : "r"(a[0]), "r"(a[1]), "r"(a[2]), "r"(a[3]), "r"(b[0]), "r"(b[1]));
}
__device__ __forceinline__ void st4(uint32_t a, uint32_t x, uint32_t y, uint32_t z, uint32_t w) {
    asm volatile("st.shared.v4.u32 [%0], {%1,%2,%3,%4};" :: "r"(a), "r"(x), "r"(y), "r"(z), "r"(w));
}

__device__ __forceinline__ void split16(float x, unsigned short& hi, unsigned short& lo) {
    uint32_t bx = __float_as_uint(x);
    hi = (unsigned short)(bx >> 16);
    float lf = x - __uint_as_float(bx & 0xFFFF0000u);
    lo = (unsigned short)(__float_as_uint(lf) >> 16);
}

// ---------------- K0 ----------------------------------------------------------
__global__ void k_hw(const float* __restrict__ hidden, const float* __restrict__ Wen) {
    int b = blockIdx.x, tid = threadIdx.x;
    float p = 0.f;
    for (int k = tid; k < HH; k += 128) p += hidden[b * HH + k] * Wen[k];
    __shared__ float red[128];
    red[tid] = p; __syncthreads();
    for (int o = 64; o >= 32; o >>= 1) { if (tid < o) red[tid] += red[tid + o]; __syncthreads(); }
    if (tid < 32) {
        float v = red[tid];
        for (int o = 16; o; o >>= 1) v += __shfl_xor_sync(~0u, v, o);
        if (tid == 0) g_hw[b] = v;
    }
}

// ---------------- K1: attention (16 rows per CTA, 2 stages, online softmax) ---
__global__ __launch_bounds__(256)
void k_attn(const float* __restrict__ enc, const float* __restrict__ Wen,
            const float* __restrict__ be) {
    extern __shared__ float sm[];
    float* rows = sm;                 // [8][2048]
    float* we   = sm + CROWS * TWOH;  // [2048]
    __shared__ float sE[CROWS];
    const int chunk = blockIdx.x, b = blockIdx.y, tid = threadIdx.x;
    const int w = tid >> 5, lane = tid & 31;
    uint32_t s_rows = (uint32_t)__cvta_generic_to_shared(rows);
    uint32_t s_we   = (uint32_t)__cvta_generic_to_shared(we);

    // stage w_e once
    for (int i = tid; i < TWOH / 4; i += 256)
        cpa16(s_we + i * 16, (const float4*)(Wen + HH) + i);

    float ctx[8];
#pragma unroll
    for (int i = 0; i < 8; i++) ctx[i] = 0.f;
    float M = -1e30f, L = 0.f;

    const float hwb = g_hw[b];
    const float bev = be[0];

#pragma unroll
    for (int st = 0; st < 2; st++) {
        const int s0 = chunk * 16 + st * CROWS;
        for (int i = tid; i < CROWS * (TWOH / 4); i += 256) {
            int r = i >> 9, c = i & 511;
            cpa16(s_rows + (r * (TWOH / 4) + c) * 16,
                  (const float4*)(enc + ((size_t)(s0 + r) * BB + b) * TWOH) + c);
        }
        cpa_commit(); cpa_wait0();
        __syncthreads();

        // energies: 8 warps x 1 row
        {
            float p = 0.f;
            const float* row = rows + w * TWOH;
            for (int j = lane; j < TWOH; j += 32) p += row[j] * we[j];
            for (int o = 16; o; o >>= 1) p += __shfl_xor_sync(~0u, p, o);
            if (lane == 0) sE[w] = fmaxf(p + hwb + bev, 0.f);
        }
        __syncthreads();

        float m2 = M;
#pragma unroll
        for (int i = 0; i < CROWS; i++) m2 = fmaxf(m2, sE[i]);
        float pe[CROWS];
        float lst = 0.f;
#pragma unroll
        for (int i = 0; i < CROWS; i++) { pe[i] = __expf(sE[i] - m2); lst += pe[i]; }
        float scale = __expf(M - m2);
        L = L * scale + lst;
        M = m2;
#pragma unroll
        for (int q = 0; q < 8; q++) {
            int d = q * 256 + tid;
            float v = ctx[q] * scale;
#pragma unroll
            for (int i = 0; i < CROWS; i++) v += pe[i] * rows[i * TWOH + d];
            ctx[q] = v;
        }
        if (st == 0) __syncthreads();   // rows reused next stage
    }

    float* dst = g_ctx + ((size_t)b * NCHUNK + chunk) * TWOH;
#pragma unroll
    for (int q = 0; q < 8; q++) dst[q * 256 + tid] = ctx[q];
    if (tid == 0) { g_eM[b * NCHUNK + chunk] = M; g_eL[b * NCHUNK + chunk] = L; }
}

// ---------------- K2: combine (8-way parallel over features) ----------------
__global__ void k_combine(const float* __restrict__ emb_table,
                          const int* __restrict__ x,
                          const float* __restrict__ hidden) {
    int b = blockIdx.x, y = blockIdx.y, tid = threadIdx.x;
    __shared__ float ssc[NCHUNK];
    __shared__ float sInv;
    if (tid == 0) {
        float M = -1e30f;
        for (int i = 0; i < NCHUNK; i++) M = fmaxf(M, g_eM[b * NCHUNK + i]);
        float L = 0.f;
        for (int i = 0; i < NCHUNK; i++) {
            float s = __expf(g_eM[b * NCHUNK + i] - M);
            ssc[i] = s;
            L += s * g_eL[b * NCHUNK + i];
        }
        sInv = 1.f / L;
    }
    __syncthreads();
    float inv = sInv;
    unsigned short hi, lo;
    {
        int d = y * 256 + tid;
        float v = 0.f;
#pragma unroll 8
        for (int i = 0; i < NCHUNK; i++)
            v += ssc[i] * g_ctx[((size_t)b * NCHUNK + i) * TWOH + d];
        split16(v * inv, hi, lo);
        g_Bhi[b * KTOT + d] = hi; g_Blo[b * KTOT + d] = lo;
    }
    int xb = x[b];
    if (tid < 64) {
        int j = y * 64 + tid;
        split16(emb_table[(size_t)xb * EE + j], hi, lo);
        g_Bhi[b * KTOT + TWOH + j] = hi; g_Blo[b * KTOT + TWOH + j] = lo;
    }
    if (tid < 128) {
        int j = y * 128 + tid;
        split16(hidden[b * HH + j], hi, lo);
        g_Bhi[b * KTOT + TWOH + EE + j] = hi; g_Blo[b * KTOT + TWOH + EE + j] = lo;
    }
}

// ================= MT=128 GEMM pieces (gates, R10-proven) ======================
__device__ __forceinline__ void stsA128(uint32_t sb, const float4* pa, int cm, int ckq) {
    uint32_t h[8], lw[8];
#pragma unroll
    for (int i = 0; i < 4; i++) {
        uint32_t bx = __float_as_uint(pa[i].x), by = __float_as_uint(pa[i].y);
        uint32_t bz = __float_as_uint(pa[i].z), bw = __float_as_uint(pa[i].w);
        h[2 * i]     = __byte_perm(bx, by, 0x7632);
        h[2 * i + 1] = __byte_perm(bz, bw, 0x7632);
        float lx = pa[i].x - __uint_as_float(bx & 0xFFFF0000u);
        float ly = pa[i].y - __uint_as_float(by & 0xFFFF0000u);
        float lz = pa[i].z - __uint_as_float(bz & 0xFFFF0000u);
        float lv = pa[i].w - __uint_as_float(bw & 0xFFFF0000u);
        lw[2 * i]     = __byte_perm(__float_as_uint(lx), __float_as_uint(ly), 0x7632);
        lw[2 * i + 1] = __byte_perm(__float_as_uint(lz), __float_as_uint(lv), 0x7632);
    }
    uint32_t d = sb + G_AHI + cm * 80 + ckq * 2;
    st4(d, h[0], h[1], h[2], h[3]);
    st4(d + 16, h[4], h[5], h[6], h[7]);
    d = sb + G_ALO + cm * 80 + ckq * 2;
    st4(d, lw[0], lw[1], lw[2], lw[3]);
    st4(d + 16, lw[4], lw[5], lw[6], lw[7]);
}

__device__ __forceinline__ void domma128(uint32_t sb, float (*acc)[4], int w, int l) {
    const int arow = w * 16 + (l & 7) + ((l >> 3) & 1) * 8;
    const int acol = ((l >> 4) & 1) * 8;
    const int brof = ((l >> 4) & 1) * 8 + (l & 7);
    const int bcol = ((l >> 3) & 1) * 8;
#pragma unroll
    for (int ks = 0; ks < 2; ks++) {
        uint32_t ahi[4], alo[4];
        uint32_t ao = arow * 80 + (ks * 16 + acol) * 2;
        ldsm4(ahi, sb + G_AHI + ao);
        ldsm4(alo, sb + G_ALO + ao);
#pragma unroll
        for (int p = 0; p < 4; p++) {
            uint32_t bh[4], bl[4];
            uint32_t bo = (p * 16 + brof) * 80 + (ks * 16 + bcol) * 2;
            ldsm4(bh, sb + G_BHI + bo);
            ldsm4(bl, sb + G_BLO + bo);
            mma16816(acc[2 * p],     ahi, bh);
            mma16816(acc[2 * p + 1], ahi, bh + 2);
            mma16816(acc[2 * p],     alo, bh);
            mma16816(acc[2 * p + 1], alo, bh + 2);
            mma16816(acc[2 * p],     ahi, bl);
            mma16816(acc[2 * p + 1], ahi, bl + 2);
        }
    }
}

// ---------------- K3: gates GEMM  grid(32, 14), MT=128 ------------------------
__global__ __launch_bounds__(256, 3)
void k_gates_mm(const float* __restrict__ Wih, const float* __restrict__ Whh) {
    extern __shared__ char dsm[];
    uint32_t base = (uint32_t)__cvta_generic_to_shared(dsm);
    const int tid = threadIdx.x, w = tid >> 5, l = tid & 31;
    const int mbase = blockIdx.x * GMT;
    const int split = blockIdx.y;
    const int kstart = split * KSPLIT;
    const int NCH = KSPLIT / KC;     // 8

    const int cm = tid >> 1, ckq = (tid & 1) * 16;
    const int bn = tid >> 2, bq = (tid & 3) * 16;

    float acc[8][4];
#pragma unroll
    for (int i = 0; i < 8; i++)
#pragma unroll
        for (int j = 0; j < 4; j++) acc[i][j] = 0.f;

    float4 pa[4];
    auto ldgA = [&](int kg) {
        const float* src = (kg < 2560)
            ? Wih + (size_t)(mbase + cm) * 2560 + kg
            : Whh + (size_t)(mbase + cm) * 1024 + (kg - 2560);
#pragma unroll
        for (int i = 0; i < 4; i++) pa[i] = *(const float4*)(src + ckq + i * 4);
    };
    auto cpaB = [&](int kg, uint32_t sb) {
        cpa16(sb + G_BHI + bn * 80 + bq, (const char*)g_Bhi + (size_t)bn * KTOT * 2 + kg * 2 + bq);
        cpa16(sb + G_BLO + bn * 80 + bq, (const char*)g_Blo + (size_t)bn * KTOT * 2 + kg * 2 + bq);
        cpa_commit();
    };

    ldgA(kstart);
    cpaB(kstart, base);
    for (int c = 0; c < NCH; c++) {
        uint32_t sb = base + (c & 1) * G_STAGE;
        stsA128(sb, pa, cm, ckq);
        cpa_wait0();
        __syncthreads();
        if (c + 1 < NCH) {
            int kg = kstart + (c + 1) * KC;
            ldgA(kg);
            cpaB(kg, base + ((c + 1) & 1) * G_STAGE);
        }
        domma128(sb, acc, w, l);
        __syncthreads();
    }

    const int gid = l >> 2, tig = (l & 3) * 2;
    float* outp = g_gatesP + ((size_t)split * G4 + mbase + w * 16) * BB;
#pragma unroll
    for (int no = 0; no < 8; no++) {
        *(float2*)(outp + gid * BB + no * 8 + tig)       = make_float2(acc[no][0], acc[no][1]);
        *(float2*)(outp + (gid + 8) * BB + no * 8 + tig) = make_float2(acc[no][2], acc[no][3]);
    }
}

// ---------------- K3b: LSTM ---------------------------------------------------
__global__ void k_lstm(const float* __restrict__ b_ih, const float* __restrict__ b_hh,
                       const float* __restrict__ cell,
                       float* __restrict__ h1o, float* __restrict__ c1o) {
    int idx = blockIdx.x * blockDim.x + threadIdx.x;
    int b = idx & 63, j = idx >> 6;
    float gi = 0, gf = 0, gg = 0, go = 0;
#pragma unroll
    for (int s = 0; s < NSPLIT; s++) {
        const float* gp = g_gatesP + (size_t)s * G4 * BB;
        gi += gp[(j) * BB + b];
        gf += gp[(1024 + j) * BB + b];
        gg += gp[(2048 + j) * BB + b];
        go += gp[(3072 + j) * BB + b];
    }
    gi += b_ih[j]        + b_hh[j];
    gf += b_ih[1024 + j] + b_hh[1024 + j];
    gg += b_ih[2048 + j] + b_hh[2048 + j];
    go += b_ih[3072 + j] + b_hh[3072 + j];
    float c0 = cell[b * HH + j];
    float c1 = sigm(gf) * c0 + sigm(gi) * tanhf(gg);
    float h1 = sigm(go) * tanhf(c1);
    h1o[b * HH + j] = h1;
    c1o[b * HH + j] = c1;
    unsigned short hi, lo;
    split16(h1, hi, lo);
    g_h1hi[b * HH + j] = hi;
    g_h1lo[b * HH + j] = lo;
}

// ================= MT=64 GEMM pieces (fc, R12-proven) ==========================
__device__ __forceinline__ void stsA64(uint32_t sb, const float4* pa, int row, int qq) {
    uint32_t h[4], lw[4];
#pragma unroll
    for (int i = 0; i < 2; i++) {
        uint32_t bx = __float_as_uint(pa[i].x), by = __float_as_uint(pa[i].y);
        uint32_t bz = __float_as_uint(pa[i].z), bw = __float_as_uint(pa[i].w);
        h[2 * i]     = __byte_perm(bx, by, 0x7632);
        h[2 * i + 1] = __byte_perm(bz, bw, 0x7632);
        float lx = pa[i].x - __uint_as_float(bx & 0xFFFF0000u);
        float ly = pa[i].y - __uint_as_float(by & 0xFFFF0000u);
        float lz = pa[i].z - __uint_as_float(bz & 0xFFFF0000u);
        float lv = pa[i].w - __uint_as_float(bw & 0xFFFF0000u);
        lw[2 * i]     = __byte_perm(__float_as_uint(lx), __float_as_uint(ly), 0x7632);
        lw[2 * i + 1] = __byte_perm(__float_as_uint(lz), __float_as_uint(lv), 0x7632);
    }
    uint32_t d = sb + F_AHI + row * 80 + qq * 2;
    st4(d, h[0], h[1], h[2], h[3]);
    d = sb + F_ALO + row * 80 + qq * 2;
    st4(d, lw[0], lw[1], lw[2], lw[3]);
}

__device__ __forceinline__ void domma64(uint32_t sb, float (*acc)[4], int w, int l) {
    const int wq = w & 3, wh = w >> 2;
    const int arow = wq * 16 + (l & 7) + ((l >> 3) & 1) * 8;
    const int acol = ((l >> 4) & 1) * 8;
    const int brof = wh * 32 + ((l >> 4) & 1) * 8 + (l & 7);
    const int bcol = ((l >> 3) & 1) * 8;
#pragma unroll
    for (int ks = 0; ks < 2; ks++) {
        uint32_t ahi[4], alo[4];
        uint32_t ao = arow * 80 + (ks * 16 + acol) * 2;
        ldsm4(ahi, sb + F_AHI + ao);
        ldsm4(alo, sb + F_ALO + ao);
#pragma unroll
        for (int p = 0; p < 2; p++) {
            uint32_t bh[4], bl[4];
            uint32_t bo = (p * 16 + brof) * 80 + (ks * 16 + bcol) * 2;
            ldsm4(bh, sb + F_BHI + bo);
            ldsm4(bl, sb + F_BLO + bo);
            mma16816(acc[2 * p],     ahi, bh);
            mma16816(acc[2 * p + 1], ahi, bh + 2);
            mma16816(acc[2 * p],     alo, bh);
            mma16816(acc[2 * p + 1], alo, bh + 2);
            mma16816(acc[2 * p],     ahi, bl);
            mma16816(acc[2 * p + 1], ahi, bl + 2);
        }
    }
}

// ---------------- K4: FC GEMM  grid(500), K=1024, MT=64 -----------------------
__global__ __launch_bounds__(256, 4)
void k_fc_mm(const float* __restrict__ Wfc, const float* __restrict__ bfc,
             float* __restrict__ pred) {
    extern __shared__ char dsm[];
    uint32_t base = (uint32_t)__cvta_generic_to_shared(dsm);
    const int tid = threadIdx.x, w = tid >> 5, l = tid & 31;
    const int mbase = blockIdx.x * FMT;
    const int NCH = HH / KC;         // 32

    const int arow = tid >> 2, aqq = (tid & 3) * 8;
    const int bn = tid >> 2, bq = (tid & 3) * 16;

    float acc[4][4];
#pragma unroll
    for (int i = 0; i < 4; i++)
#pragma unroll
        for (int j = 0; j < 4; j++) acc[i][j] = 0.f;

    float4 pa[2];
    auto ldgA = [&](int kg) {
        const float* src = Wfc + (size_t)(mbase + arow) * HH + kg;
        pa[0] = *(const float4*)(src + aqq);
        pa[1] = *(const float4*)(src + aqq + 4);
    };
    auto cpaB = [&](int kg, uint32_t sb) {
        cpa16(sb + F_BHI + bn * 80 + bq, (const char*)g_h1hi + (size_t)bn * HH * 2 + kg * 2 + bq);
        cpa16(sb + F_BLO + bn * 80 + bq, (const char*)g_h1lo + (size_t)bn * HH * 2 + kg * 2 + bq);
        cpa_commit();
    };

    ldgA(0);
    cpaB(0, base);
    for (int c = 0; c < NCH; c++) {
        uint32_t sb = base + (c & 1) * F_STAGE;
        stsA64(sb, pa, arow, aqq);
        cpa_wait0();
        __syncthreads();
        if (c + 1 < NCH) {
            int kg = (c + 1) * KC;
            ldgA(kg);
            cpaB(kg, base + ((c + 1) & 1) * F_STAGE);
        }
        domma64(sb, acc, w, l);
        __syncthreads();
    }
    __syncthreads();

    float* ts = (float*)dsm;
    const int wq = w & 3, wh = w >> 2;
    const int gid = l >> 2, tig = (l & 3) * 2;
    float bias0 = bfc[mbase + wq * 16 + gid];
    float bias1 = bfc[mbase + wq * 16 + gid + 8];
#pragma unroll
    for (int j = 0; j < 4; j++) {
        int n = wh * 32 + j * 8 + tig;
        ts[n * 68 + wq * 16 + gid]           = acc[j][0] + bias0;
        ts[(n + 1) * 68 + wq * 16 + gid]     = acc[j][1] + bias0;
        ts[n * 68 + wq * 16 + gid + 8]       = acc[j][2] + bias1;
        ts[(n + 1) * 68 + wq * 16 + gid + 8] = acc[j][3] + bias1;
    }
    __syncthreads();
    {
        int b = tid >> 2, q = tid & 3;
        const float* srow = ts + b * 68 + q * 16;
        float* drow = pred + (size_t)b * VV + mbase + q * 16;
#pragma unroll
        for (int i = 0; i < 4; i++)
            *(float4*)(drow + i * 4) = make_float4(srow[i * 4], srow[i * 4 + 1],
                                                   srow[i * 4 + 2], srow[i * 4 + 3]);
    }
}

// ---------------- launch --------------------------------------------------------
extern "C" void kernel_launch(void* const* d_in, const int* in_sizes, int n_in,
                              void* d_out, int out_size) {
    const int*   x       = (const int*)  d_in[0];
    const float* enc     = (const float*)d_in[1];
    const float* hidden  = (const float*)d_in[2];
    const float* cell    = (const float*)d_in[3];
    const float* emb     = (const float*)d_in[4];
    const float* Wen     = (const float*)d_in[5];
    const float* be      = (const float*)d_in[6];
    const float* Wih     = (const float*)d_in[7];
    const float* Whh     = (const float*)d_in[8];
    const float* b_ih    = (const float*)d_in[9];
    const float* b_hh    = (const float*)d_in[10];
    const float* Wfc     = (const float*)d_in[11];
    const float* bfc     = (const float*)d_in[12];

    float* pred = (float*)d_out;
    float* h1o  = pred + (size_t)BB * VV;
    float* c1o  = h1o + (size_t)BB * HH;

    const int smem_attn = (CROWS * TWOH + TWOH) * sizeof(float);   // 72 KB
    cudaFuncSetAttribute(k_attn, cudaFuncAttributeMaxDynamicSharedMemorySize, smem_attn);
    cudaFuncSetAttribute(k_gates_mm, cudaFuncAttributeMaxDynamicSharedMemorySize, 2 * G_STAGE);
    cudaFuncSetAttribute(k_fc_mm, cudaFuncAttributeMaxDynamicSharedMemorySize, 2 * F_STAGE);

    k_hw<<<BB, 128>>>(hidden, Wen);
    k_attn<<<dim3(NCHUNK, BB), 256, smem_attn>>>(enc, Wen, be);
    k_combine<<<dim3(BB, 8), 256>>>(emb, x, hidden);
    k_gates_mm<<<dim3(G4 / GMT, NSPLIT), 256, 2 * G_STAGE>>>(Wih, Whh);
    k_lstm<<<(BB * HH) / 256, 256>>>(b_ih, b_hh, cell, h1o, c1o);
    k_fc_mm<<<VV / FMT, 256, 2 * F_STAGE>>>(Wfc, bfc, pred);
}